// round 2
// baseline (speedup 1.0000x reference)
#include <cuda_runtime.h>
#include <cuda_bf16.h>

// Problem constants
#define NN 200000
#define MM 200
#define DM 100
#define DE 172
#define EE 8192
#define KK 10
#define NEF 400000
#define TAU 2.0f

#define E2 (2*EE)     // 16384
#define E3 (3*EE)     // 24576

// ----------------- persistent scratch (zero-initialized at load) -----------------
__device__ float g_A1[E2 * 400];        // [mem_s||mem_g] gathered for merge (src rows 0..E, dst rows E..2E)
__device__ float g_merged12[E2 * MM];   // src_m rows 0..E, dst_m rows E..2E
__device__ float g_Amsg[E2 * 572];      // concat for message MLP
__device__ float g_msgs[E2 * DM];       // msg_s rows 0..E, msg_g rows E..2E
__device__ float g_Ah[E2 * MM];         // gathered h rows (mem_s[src] / mem_g[dst])
__device__ float g_gh[E2 * 600];
__device__ float g_gx[E2 * 600];
__device__ float g_prop[E2 * MM];
__device__ float g_delta_s[(long)NN * MM];  // sparse-touched delta arrays
__device__ float g_delta_g[(long)NN * MM];
__device__ int   g_last_s[NN];
__device__ int   g_last_g[NN];
__device__ float g_A3[E3 * 400];
__device__ float g_merged3[E3 * MM];
__device__ float g_proj[E3 * DM];

// ----------------- zero / init touched rows -----------------
// tasks: [0,E): src rows (side s, also last_s=-1); [E,2E): dst rows (side g, last_g=-1);
// [2E, 2E+E*K): neighbors of src (side s); then neighbors of dst (side g).
__global__ void zero_init_kernel(const int* __restrict__ src, const int* __restrict__ dst,
                                 const int* __restrict__ neighbors)
{
    int t = blockIdx.x;
    int tid = threadIdx.x;
    float* delta;
    int node;
    if (t < EE) {
        node = src[t]; delta = g_delta_s;
        if (tid == 0) g_last_s[node] = -1;
    } else if (t < E2) {
        node = dst[t - EE]; delta = g_delta_g;
        if (tid == 0) g_last_g[node] = -1;
    } else if (t < E2 + EE*KK) {
        int q = t - E2;
        node = neighbors[(long)src[q / KK] * KK + (q % KK)];
        delta = g_delta_s;
    } else {
        int q = t - E2 - EE*KK;
        node = neighbors[(long)dst[q / KK] * KK + (q % KK)];
        delta = g_delta_g;
    }
    if (tid < MM) delta[(long)node * MM + tid] = 0.0f;
}

__global__ void last_occ_kernel(const int* __restrict__ src, const int* __restrict__ dst)
{
    int e = blockIdx.x * blockDim.x + threadIdx.x;
    if (e >= EE) return;
    atomicMax(&g_last_s[src[e]], e);
    atomicMax(&g_last_g[dst[e]], e);
}

// ----------------- prep (gather) kernels: one block per row -----------------
__global__ void prep_A1_kernel(const float* __restrict__ mem_s, const float* __restrict__ mem_g,
                               const int* __restrict__ src, const int* __restrict__ dst)
{
    int r = blockIdx.x;                       // 0..2E
    int idx = (r < EE) ? src[r] : dst[r - EE];
    const float* ps = mem_s + (long)idx * MM;
    const float* pg = mem_g + (long)idx * MM;
    for (int c = threadIdx.x; c < 400; c += blockDim.x)
        g_A1[(long)r * 400 + c] = (c < MM) ? ps[c] : pg[c - MM];
}

__global__ void prep_Amsg_kernel(const float* __restrict__ edge_feats,
                                 const int* __restrict__ edge_idxs)
{
    int r = blockIdx.x;                       // 0..2E
    int e = (r < EE) ? r : (r - EE);
    // row r<E (msg_s): [src_m | dst_m | ef] ; row>=E (msg_g): [dst_m | src_m | ef]
    const float* first  = (r < EE) ? (g_merged12 + (long)e * MM) : (g_merged12 + (long)(EE + e) * MM);
    const float* second = (r < EE) ? (g_merged12 + (long)(EE + e) * MM) : (g_merged12 + (long)e * MM);
    const float* ef = edge_feats + (long)edge_idxs[e] * DE;
    for (int c = threadIdx.x; c < 572; c += blockDim.x) {
        float v;
        if (c < MM)            v = first[c];
        else if (c < 2*MM)     v = second[c - MM];
        else                   v = ef[c - 2*MM];
        g_Amsg[(long)r * 572 + c] = v;
    }
}

__global__ void prep_Ah_kernel(const float* __restrict__ mem_s, const float* __restrict__ mem_g,
                               const int* __restrict__ src, const int* __restrict__ dst)
{
    int r = blockIdx.x;
    const float* p = (r < EE) ? (mem_s + (long)src[r] * MM) : (mem_g + (long)dst[r - EE] * MM);
    for (int c = threadIdx.x; c < MM; c += blockDim.x)
        g_Ah[(long)r * MM + c] = p[c];
}

__global__ void prep_A3_kernel(const float* __restrict__ mem_s, const float* __restrict__ mem_g,
                               const int* __restrict__ src, const int* __restrict__ dst,
                               const int* __restrict__ neg)
{
    int r = blockIdx.x;                       // 0..3E
    int idx;
    if (r < EE)       idx = src[r];
    else if (r < E2)  idx = dst[r - EE];
    else              idx = neg[r - E2];
    const float* ps = mem_s + (long)idx * MM;
    const float* pg = mem_g + (long)idx * MM;
    const float* ds = g_delta_s + (long)idx * MM;
    const float* dg = g_delta_g + (long)idx * MM;
    for (int c = threadIdx.x; c < 400; c += blockDim.x) {
        float v = (c < MM) ? (ps[c] + ds[c]) : (pg[c - MM] + dg[c - MM]);
        g_A3[(long)r * 400 + c] = v;
    }
}

// ----------------- generic tiled GEMM with fused bias/activation -----------------
// C[Mrows x Ndim] = act(A[Mrows x Kdim] @ B + bias); B/bias switch at row rowSwitch.
// act: 0 none, 1 tanh, 2 relu
#define BM 128
#define BN 64
#define BKT 16
__global__ __launch_bounds__(256) void gemm_kernel(
    const float* __restrict__ A, int Kdim,
    const float* __restrict__ B0, const float* __restrict__ B1,
    const float* __restrict__ bias0, const float* __restrict__ bias1,
    int rowSwitch,
    float* __restrict__ C, int Mrows, int Ndim, int act)
{
    __shared__ float As[BKT][BM + 4];
    __shared__ float Bs[BKT][BN];
    int blockRow = blockIdx.y * BM;
    int blockCol = blockIdx.x * BN;
    const float* B    = (blockRow < rowSwitch) ? B0 : B1;
    const float* bias = (blockRow < rowSwitch) ? bias0 : bias1;
    int tid = threadIdx.x;
    int tx = tid & 15;       // col group
    int ty = tid >> 4;       // row group
    float acc[8][4];
    #pragma unroll
    for (int i = 0; i < 8; i++)
        #pragma unroll
        for (int j = 0; j < 4; j++) acc[i][j] = 0.0f;

    for (int k0 = 0; k0 < Kdim; k0 += BKT) {
        #pragma unroll
        for (int i = 0; i < 8; i++) {
            int idx = tid + i * 256;             // 0..2047
            int m  = idx >> 4;                   // /16
            int kk = idx & 15;
            int r = blockRow + m, k = k0 + kk;
            float v = 0.0f;
            if (r < Mrows && k < Kdim) v = A[(long)r * Kdim + k];
            As[kk][m] = v;
        }
        #pragma unroll
        for (int i = 0; i < 4; i++) {
            int idx = tid + i * 256;             // 0..1023
            int kk = idx >> 6;                   // /64
            int n  = idx & 63;
            int k = k0 + kk, nn = blockCol + n;
            float v = 0.0f;
            if (k < Kdim && nn < Ndim) v = B[(long)k * Ndim + nn];
            Bs[kk][n] = v;
        }
        __syncthreads();
        #pragma unroll
        for (int kk = 0; kk < BKT; kk++) {
            float a[8], b[4];
            #pragma unroll
            for (int i = 0; i < 8; i++) a[i] = As[kk][ty * 8 + i];
            #pragma unroll
            for (int j = 0; j < 4; j++) b[j] = Bs[kk][tx * 4 + j];
            #pragma unroll
            for (int i = 0; i < 8; i++)
                #pragma unroll
                for (int j = 0; j < 4; j++)
                    acc[i][j] = fmaf(a[i], b[j], acc[i][j]);
        }
        __syncthreads();
    }
    #pragma unroll
    for (int i = 0; i < 8; i++) {
        int r = blockRow + ty * 8 + i;
        if (r >= Mrows) continue;
        #pragma unroll
        for (int j = 0; j < 4; j++) {
            int n = blockCol + tx * 4 + j;
            if (n >= Ndim) continue;
            float v = acc[i][j];
            if (bias) v += bias[n];
            if (act == 1) v = tanhf(v);
            else if (act == 2) v = fmaxf(v, 0.0f);
            C[(long)r * Ndim + n] = v;
        }
    }
}

// ----------------- GRU + neighbor-propagation scatter -----------------
__device__ __forceinline__ float sigmoidf_(float x) { return 1.0f / (1.0f + expf(-x)); }

__global__ void gru_scatter_kernel(const int* __restrict__ src, const int* __restrict__ dst,
                                   const int* __restrict__ neighbors,
                                   const float* __restrict__ times,
                                   const float* __restrict__ lu_s, const float* __restrict__ lu_g)
{
    int row = blockIdx.x;                 // 0..2E
    bool sideS = (row < EE);
    int e = sideS ? row : (row - EE);
    int node = sideS ? src[e] : dst[e];
    int last = sideS ? g_last_s[node] : g_last_g[node];
    if (last != e) return;                // not the last message for this node
    int m = threadIdx.x;
    if (m >= MM) return;

    float* delta = sideS ? g_delta_s : g_delta_g;
    const float* lu = sideS ? lu_s : lu_g;

    float h  = g_Ah[(long)row * MM + m];
    long gb = (long)row * 600;
    float rx = g_gx[gb + m],        zx = g_gx[gb + MM + m],  nx = g_gx[gb + 2*MM + m];
    float rh = g_gh[gb + m],        zh = g_gh[gb + MM + m],  nh = g_gh[gb + 2*MM + m];
    float r = sigmoidf_(rx + rh);
    float z = sigmoidf_(zx + zh);
    float n = tanhf(nx + r * nh);
    float new_h = (1.0f - z) * n + z * h;
    atomicAdd(&delta[(long)node * MM + m], new_h - h);

    float p = g_prop[(long)row * MM + m];
    float t = times[e];
    #pragma unroll
    for (int k = 0; k < KK; k++) {
        int nb = neighbors[(long)node * KK + k];
        float dt = t - lu[nb];
        dt = fminf(fmaxf(dt, 0.0f), 50.0f);
        float decay = expf(-dt * (1.0f / TAU));
        atomicAdd(&delta[(long)nb * MM + m], decay * p);
    }
}

// ----------------- final dot + sigmoid -----------------
__global__ void score_kernel(float* __restrict__ out)
{
    int gw = (blockIdx.x * blockDim.x + threadIdx.x) >> 5;   // global warp id = output index
    int lane = threadIdx.x & 31;
    if (gw >= E2) return;
    int e = (gw < EE) ? gw : (gw - EE);
    const float* u = g_proj + (long)e * DM;                                   // src proj (W_s)
    const float* v = g_proj + (long)((gw < EE) ? (EE + e) : (E2 + e)) * DM;   // dst/neg proj (W_g)
    float s = 0.0f;
    for (int c = lane; c < DM; c += 32) s += u[c] * v[c];
    #pragma unroll
    for (int off = 16; off > 0; off >>= 1) s += __shfl_down_sync(0xffffffffu, s, off);
    if (lane == 0) out[gw] = 1.0f / (1.0f + expf(-s));
}

// ----------------- launch -----------------
extern "C" void kernel_launch(void* const* d_in, const int* in_sizes, int n_in,
                              void* d_out, int out_size)
{
    const float* mem_s   = (const float*)d_in[0];
    const float* mem_g   = (const float*)d_in[1];
    const float* lu_s    = (const float*)d_in[2];
    const float* lu_g    = (const float*)d_in[3];
    const float* efeats  = (const float*)d_in[4];
    const float* etimes  = (const float*)d_in[5];
    const int*   src     = (const int*)d_in[6];
    const int*   dst     = (const int*)d_in[7];
    const int*   neg     = (const int*)d_in[8];
    const int*   eidx    = (const int*)d_in[9];
    const int*   nbrs    = (const int*)d_in[10];
    const float* W_merge = (const float*)d_in[11];
    const float* b_merge = (const float*)d_in[12];
    const float* W_msg   = (const float*)d_in[13];
    const float* b_msg   = (const float*)d_in[14];
    const float* Wx_s    = (const float*)d_in[15];
    const float* Wh_s    = (const float*)d_in[16];
    const float* bg_s    = (const float*)d_in[17];
    const float* Wx_g    = (const float*)d_in[18];
    const float* Wh_g    = (const float*)d_in[19];
    const float* bg_g    = (const float*)d_in[20];
    const float* Wp_s    = (const float*)d_in[21];
    const float* Wp_g    = (const float*)d_in[22];
    const float* W_s     = (const float*)d_in[23];
    const float* W_g     = (const float*)d_in[24];
    float* out = (float*)d_out;

    // Real DEVICE addresses of the __device__ scratch arrays.
    // (Passing the symbol name from host code yields the host shadow — on GB300
    //  ATS that silently "works" but reads/writes host memory. Must use
    //  cudaGetSymbolAddress for device-side pointers.)
    float *pA1, *pMerged12, *pAmsg, *pMsgs, *pAh, *pGh, *pGx, *pProp, *pA3, *pMerged3, *pProj;
    cudaGetSymbolAddress((void**)&pA1,       g_A1);
    cudaGetSymbolAddress((void**)&pMerged12, g_merged12);
    cudaGetSymbolAddress((void**)&pAmsg,     g_Amsg);
    cudaGetSymbolAddress((void**)&pMsgs,     g_msgs);
    cudaGetSymbolAddress((void**)&pAh,       g_Ah);
    cudaGetSymbolAddress((void**)&pGh,       g_gh);
    cudaGetSymbolAddress((void**)&pGx,       g_gx);
    cudaGetSymbolAddress((void**)&pProp,     g_prop);
    cudaGetSymbolAddress((void**)&pA3,       g_A3);
    cudaGetSymbolAddress((void**)&pMerged3,  g_merged3);
    cudaGetSymbolAddress((void**)&pProj,     g_proj);

    const int BIG = 1 << 30;

    // 1. zero touched delta rows + init last_occ
    zero_init_kernel<<<2 * EE * (KK + 1), 256>>>(src, dst, nbrs);
    // 2. last occurrence per node
    last_occ_kernel<<<(EE + 255) / 256, 256>>>(src, dst);

    // 3. merge(src), merge(dst)
    prep_A1_kernel<<<E2, 256>>>(mem_s, mem_g, src, dst);
    {
        dim3 grid((MM + BN - 1) / BN, (E2 + BM - 1) / BM);
        gemm_kernel<<<grid, 256>>>(pA1, 400, W_merge, W_merge, b_merge, b_merge, BIG,
                                   pMerged12, E2, MM, 1);
    }
    // 4. messages
    prep_Amsg_kernel<<<E2, 256>>>(efeats, eidx);
    {
        dim3 grid((DM + BN - 1) / BN, (E2 + BM - 1) / BM);
        gemm_kernel<<<grid, 256>>>(pAmsg, 572, W_msg, W_msg, b_msg, b_msg, BIG,
                                   pMsgs, E2, DM, 2);
    }
    // 5. GRU gates + propagation vectors
    prep_Ah_kernel<<<E2, 256>>>(mem_s, mem_g, src, dst);
    {
        dim3 grid((600 + BN - 1) / BN, (E2 + BM - 1) / BM);
        gemm_kernel<<<grid, 256>>>(pAh, MM, Wh_s, Wh_g, nullptr, nullptr, EE,
                                   pGh, E2, 600, 0);
        gemm_kernel<<<grid, 256>>>(pMsgs, DM, Wx_s, Wx_g, bg_s, bg_g, EE,
                                   pGx, E2, 600, 0);
    }
    {
        dim3 grid((MM + BN - 1) / BN, (E2 + BM - 1) / BM);
        gemm_kernel<<<grid, 256>>>(pMsgs, DM, Wp_s, Wp_g, nullptr, nullptr, EE,
                                   pProp, E2, MM, 1);
    }
    // 6. GRU elementwise + scatter (delta arrays)
    gru_scatter_kernel<<<E2, 256>>>(src, dst, nbrs, etimes, lu_s, lu_g);

    // 7. score: merge updated rows, project, dot, sigmoid
    prep_A3_kernel<<<E3, 256>>>(mem_s, mem_g, src, dst, neg);
    {
        dim3 grid((MM + BN - 1) / BN, (E3 + BM - 1) / BM);
        gemm_kernel<<<grid, 256>>>(pA3, 400, W_merge, W_merge, b_merge, b_merge, BIG,
                                   pMerged3, E3, MM, 1);
    }
    {
        dim3 grid((DM + BN - 1) / BN, (E3 + BM - 1) / BM);
        gemm_kernel<<<grid, 256>>>(pMerged3, MM, W_s, W_g, nullptr, nullptr, EE,
                                   pProj, E3, DM, 0);
    }
    score_kernel<<<(E2 * 32 + 255) / 256, 256>>>(out);
}

// round 3
// speedup vs baseline: 1.5323x; 1.5323x over previous
#include <cuda_runtime.h>
#include <cuda_bf16.h>
#include <cstdint>

// Problem constants
#define NN 200000
#define MM 200
#define DM 100
#define DE 172
#define EE 8192
#define KK 10
#define TAU 2.0f

#define E2 (2*EE)     // 16384
#define E3 (3*EE)     // 24576

// ----------------- persistent scratch (zero-initialized at load) -----------------
__device__ float g_A1[E2 * 400];        // [mem_s||mem_g] gathered (src rows 0..E, dst rows E..2E)
__device__ float g_merged12[E2 * MM];
__device__ float g_Amsg[E2 * 572];
__device__ float g_msgs[E2 * DM];
__device__ float g_gh[E2 * 600];
__device__ float g_gx[E2 * 600];
__device__ float g_prop[E2 * MM];
__device__ float g_delta_s[(long)NN * MM];
__device__ float g_delta_g[(long)NN * MM];
__device__ int   g_last_s[NN];
__device__ int   g_last_g[NN];
__device__ float g_A3[E3 * 400];
__device__ float g_merged3[E3 * MM];
__device__ float g_proj[E3 * DM];

// ----------------- zero / init touched rows -----------------
__global__ void zero_init_kernel(const int* __restrict__ src, const int* __restrict__ dst,
                                 const int* __restrict__ neighbors)
{
    int t = blockIdx.x;
    int tid = threadIdx.x;
    float* delta;
    int node;
    if (t < EE) {
        node = src[t]; delta = g_delta_s;
        if (tid == 0) g_last_s[node] = -1;
    } else if (t < E2) {
        node = dst[t - EE]; delta = g_delta_g;
        if (tid == 0) g_last_g[node] = -1;
    } else if (t < E2 + EE*KK) {
        int q = t - E2;
        node = neighbors[(long)src[q / KK] * KK + (q % KK)];
        delta = g_delta_s;
    } else {
        int q = t - E2 - EE*KK;
        node = neighbors[(long)dst[q / KK] * KK + (q % KK)];
        delta = g_delta_g;
    }
    if (tid < MM) delta[(long)node * MM + tid] = 0.0f;
}

__global__ void last_occ_kernel(const int* __restrict__ src, const int* __restrict__ dst)
{
    int e = blockIdx.x * blockDim.x + threadIdx.x;
    if (e >= EE) return;
    atomicMax(&g_last_s[src[e]], e);
    atomicMax(&g_last_g[dst[e]], e);
}

// ----------------- prep (gather) kernels -----------------
__global__ void prep_A1_kernel(const float* __restrict__ mem_s, const float* __restrict__ mem_g,
                               const int* __restrict__ src, const int* __restrict__ dst)
{
    int r = blockIdx.x;                       // 0..2E
    int idx = (r < EE) ? src[r] : dst[r - EE];
    const float* ps = mem_s + (long)idx * MM;
    const float* pg = mem_g + (long)idx * MM;
    for (int c = threadIdx.x; c < 400; c += blockDim.x)
        g_A1[(long)r * 400 + c] = (c < MM) ? ps[c] : pg[c - MM];
}

__global__ void prep_Amsg_kernel(const float* __restrict__ edge_feats,
                                 const int* __restrict__ edge_idxs)
{
    int r = blockIdx.x;                       // 0..2E
    int e = (r < EE) ? r : (r - EE);
    const float* first  = (r < EE) ? (g_merged12 + (long)e * MM) : (g_merged12 + (long)(EE + e) * MM);
    const float* second = (r < EE) ? (g_merged12 + (long)(EE + e) * MM) : (g_merged12 + (long)e * MM);
    const float* ef = edge_feats + (long)edge_idxs[e] * DE;
    for (int c = threadIdx.x; c < 572; c += blockDim.x) {
        float v;
        if (c < MM)            v = first[c];
        else if (c < 2*MM)     v = second[c - MM];
        else                   v = ef[c - 2*MM];
        g_Amsg[(long)r * 572 + c] = v;
    }
}

__global__ void prep_A3_kernel(const float* __restrict__ mem_s, const float* __restrict__ mem_g,
                               const int* __restrict__ src, const int* __restrict__ dst,
                               const int* __restrict__ neg)
{
    int r = blockIdx.x;                       // 0..3E
    int idx;
    if (r < EE)       idx = src[r];
    else if (r < E2)  idx = dst[r - EE];
    else              idx = neg[r - E2];
    const float* ps = mem_s + (long)idx * MM;
    const float* pg = mem_g + (long)idx * MM;
    const float* ds = g_delta_s + (long)idx * MM;
    const float* dg = g_delta_g + (long)idx * MM;
    for (int c = threadIdx.x; c < 400; c += blockDim.x) {
        float v = (c < MM) ? (ps[c] + ds[c]) : (pg[c - MM] + dg[c - MM]);
        g_A3[(long)r * 400 + c] = v;
    }
}

// ----------------- tf32 tensor-core GEMM with fused bias/activation -----------------
// C[Mrows x Ndim] = act(A[Mrows x K] @ B + bias). B/bias/aOff switch at blockRow >= rowSwitch.
// Block: 128(M) x 64(N), 8 warps (4M x 2N), each warp 32x32 via m16n8k8 tf32 mma.
__device__ __forceinline__ uint32_t f2tf32(float f) {
    uint32_t r;
    asm("cvt.rna.tf32.f32 %0, %1;" : "=r"(r) : "f"(f));
    return r;
}

__device__ __forceinline__ void mma_tf32(float* c, const uint32_t* a, const uint32_t* b) {
    asm volatile("mma.sync.aligned.m16n8k8.row.col.f32.tf32.tf32.f32 "
                 "{%0,%1,%2,%3}, {%4,%5,%6,%7}, {%8,%9}, {%0,%1,%2,%3};"
                 : "+f"(c[0]), "+f"(c[1]), "+f"(c[2]), "+f"(c[3])
                 : "r"(a[0]), "r"(a[1]), "r"(a[2]), "r"(a[3]),
                   "r"(b[0]), "r"(b[1]));
}

__global__ __launch_bounds__(256) void gemm_tc(
    const float* __restrict__ A, int lda, int aOff0, int aOff1, int Kdim,
    const float* __restrict__ B0, const float* __restrict__ B1,
    const float* __restrict__ bias0, const float* __restrict__ bias1, int rowSwitch,
    float* __restrict__ C, int ldc, int Ndim, int act)
{
    __shared__ uint32_t As[128][36];   // stride 36: banks (4m+k)%32 -> conflict-free frag loads
    __shared__ uint32_t Bs[32][72];    // stride 72: banks (8k+n)%32 -> conflict-free frag loads
    int blockRow = blockIdx.y * 128;
    int blockCol = blockIdx.x * 64;
    bool firstSide = blockRow < rowSwitch;
    const float* B    = firstSide ? B0 : B1;
    const float* bias = firstSide ? bias0 : bias1;
    int aOff          = firstSide ? aOff0 : aOff1;

    int tid  = threadIdx.x;
    int lane = tid & 31;
    int warp = tid >> 5;
    int wm = (warp & 3) * 32;       // warp M offset within block
    int wn = (warp >> 2) * 32;      // warp N offset within block
    int g  = lane >> 2;             // group id (0..7)
    int tg = lane & 3;              // thread in group (0..3)

    float acc[2][4][4];
    #pragma unroll
    for (int i = 0; i < 2; i++)
        #pragma unroll
        for (int j = 0; j < 4; j++)
            #pragma unroll
            for (int q = 0; q < 4; q++) acc[i][j][q] = 0.0f;

    for (int k0 = 0; k0 < Kdim; k0 += 32) {
        // Stage A tile 128x32 (convert to tf32 here, coalesced gmem reads)
        #pragma unroll
        for (int i = 0; i < 16; i++) {
            int idx = tid + i * 256;
            int r = idx >> 5, k = idx & 31;
            float v = (k0 + k < Kdim) ? A[(long)(blockRow + r) * lda + aOff + k0 + k] : 0.0f;
            As[r][k] = f2tf32(v);
        }
        // Stage B tile 32x64
        #pragma unroll
        for (int i = 0; i < 8; i++) {
            int idx = tid + i * 256;
            int kr = idx >> 6, n = idx & 63;
            float v = (k0 + kr < Kdim && blockCol + n < Ndim)
                      ? B[(long)(k0 + kr) * Ndim + blockCol + n] : 0.0f;
            Bs[kr][n] = f2tf32(v);
        }
        __syncthreads();

        #pragma unroll
        for (int ks = 0; ks < 4; ks++) {
            int kb = ks * 8;
            uint32_t a[2][4], b[4][2];
            #pragma unroll
            for (int mt = 0; mt < 2; mt++) {
                int mr = wm + mt * 16 + g;
                a[mt][0] = As[mr][kb + tg];
                a[mt][1] = As[mr + 8][kb + tg];
                a[mt][2] = As[mr][kb + tg + 4];
                a[mt][3] = As[mr + 8][kb + tg + 4];
            }
            #pragma unroll
            for (int nt = 0; nt < 4; nt++) {
                int nc = wn + nt * 8 + g;
                b[nt][0] = Bs[kb + tg][nc];
                b[nt][1] = Bs[kb + tg + 4][nc];
            }
            #pragma unroll
            for (int mt = 0; mt < 2; mt++)
                #pragma unroll
                for (int nt = 0; nt < 4; nt++)
                    mma_tf32(acc[mt][nt], a[mt], b[nt]);
        }
        __syncthreads();
    }

    // Epilogue: bias + activation + guarded store
    #pragma unroll
    for (int mt = 0; mt < 2; mt++) {
        #pragma unroll
        for (int nt = 0; nt < 4; nt++) {
            int r0 = blockRow + wm + mt * 16 + g;
            int c0 = blockCol + wn + nt * 8 + tg * 2;
            float bv0 = 0.0f, bv1 = 0.0f;
            if (bias) {
                if (c0     < Ndim) bv0 = bias[c0];
                if (c0 + 1 < Ndim) bv1 = bias[c0 + 1];
            }
            #pragma unroll
            for (int q = 0; q < 4; q++) {
                int r = r0 + (q >> 1) * 8;
                int c = c0 + (q & 1);
                if (c >= Ndim) continue;
                float v = acc[mt][nt][q] + ((q & 1) ? bv1 : bv0);
                if (act == 1) v = tanhf(v);
                else if (act == 2) v = fmaxf(v, 0.0f);
                C[(long)r * ldc + c] = v;
            }
        }
    }
}

// ----------------- GRU + neighbor-propagation scatter -----------------
__device__ __forceinline__ float sigmoidf_(float x) { return 1.0f / (1.0f + expf(-x)); }

__global__ void gru_scatter_kernel(const int* __restrict__ src, const int* __restrict__ dst,
                                   const int* __restrict__ neighbors,
                                   const float* __restrict__ times,
                                   const float* __restrict__ lu_s, const float* __restrict__ lu_g)
{
    int row = blockIdx.x;                 // 0..2E
    bool sideS = (row < EE);
    int e = sideS ? row : (row - EE);
    int node = sideS ? src[e] : dst[e];
    int last = sideS ? g_last_s[node] : g_last_g[node];
    if (last != e) return;
    int m = threadIdx.x;
    if (m >= MM) return;

    float* delta = sideS ? g_delta_s : g_delta_g;
    const float* lu = sideS ? lu_s : lu_g;

    // h comes straight out of g_A1 (cols [0,200) for s-side, [200,400) for g-side)
    float h = sideS ? g_A1[(long)row * 400 + m] : g_A1[(long)row * 400 + 200 + m];
    long gb = (long)row * 600;
    float rx = g_gx[gb + m], zx = g_gx[gb + MM + m], nx = g_gx[gb + 2*MM + m];
    float rh = g_gh[gb + m], zh = g_gh[gb + MM + m], nh = g_gh[gb + 2*MM + m];
    float r = sigmoidf_(rx + rh);
    float z = sigmoidf_(zx + zh);
    float n = tanhf(nx + r * nh);
    float new_h = (1.0f - z) * n + z * h;
    atomicAdd(&delta[(long)node * MM + m], new_h - h);

    float p = g_prop[(long)row * MM + m];
    float t = times[e];
    #pragma unroll
    for (int k = 0; k < KK; k++) {
        int nb = neighbors[(long)node * KK + k];
        float dt = t - lu[nb];
        dt = fminf(fmaxf(dt, 0.0f), 50.0f);
        float decay = expf(-dt * (1.0f / TAU));
        atomicAdd(&delta[(long)nb * MM + m], decay * p);
    }
}

// ----------------- final dot + sigmoid -----------------
__global__ void score_kernel(float* __restrict__ out)
{
    int gw = (blockIdx.x * blockDim.x + threadIdx.x) >> 5;
    int lane = threadIdx.x & 31;
    if (gw >= E2) return;
    int e = (gw < EE) ? gw : (gw - EE);
    const float* u = g_proj + (long)e * DM;
    const float* v = g_proj + (long)((gw < EE) ? (EE + e) : (E2 + e)) * DM;
    float s = 0.0f;
    for (int c = lane; c < DM; c += 32) s += u[c] * v[c];
    #pragma unroll
    for (int off = 16; off > 0; off >>= 1) s += __shfl_down_sync(0xffffffffu, s, off);
    if (lane == 0) out[gw] = 1.0f / (1.0f + expf(-s));
}

// ----------------- launch -----------------
extern "C" void kernel_launch(void* const* d_in, const int* in_sizes, int n_in,
                              void* d_out, int out_size)
{
    const float* mem_s   = (const float*)d_in[0];
    const float* mem_g   = (const float*)d_in[1];
    const float* lu_s    = (const float*)d_in[2];
    const float* lu_g    = (const float*)d_in[3];
    const float* efeats  = (const float*)d_in[4];
    const float* etimes  = (const float*)d_in[5];
    const int*   src     = (const int*)d_in[6];
    const int*   dst     = (const int*)d_in[7];
    const int*   neg     = (const int*)d_in[8];
    const int*   eidx    = (const int*)d_in[9];
    const int*   nbrs    = (const int*)d_in[10];
    const float* W_merge = (const float*)d_in[11];
    const float* b_merge = (const float*)d_in[12];
    const float* W_msg   = (const float*)d_in[13];
    const float* b_msg   = (const float*)d_in[14];
    const float* Wx_s    = (const float*)d_in[15];
    const float* Wh_s    = (const float*)d_in[16];
    const float* bg_s    = (const float*)d_in[17];
    const float* Wx_g    = (const float*)d_in[18];
    const float* Wh_g    = (const float*)d_in[19];
    const float* bg_g    = (const float*)d_in[20];
    const float* Wp_s    = (const float*)d_in[21];
    const float* Wp_g    = (const float*)d_in[22];
    const float* W_s     = (const float*)d_in[23];
    const float* W_g     = (const float*)d_in[24];
    float* out = (float*)d_out;

    // Real DEVICE addresses of the __device__ scratch (host shadow trap avoided)
    float *pA1, *pMerged12, *pAmsg, *pMsgs, *pGh, *pGx, *pProp, *pA3, *pMerged3, *pProj;
    cudaGetSymbolAddress((void**)&pA1,       g_A1);
    cudaGetSymbolAddress((void**)&pMerged12, g_merged12);
    cudaGetSymbolAddress((void**)&pAmsg,     g_Amsg);
    cudaGetSymbolAddress((void**)&pMsgs,     g_msgs);
    cudaGetSymbolAddress((void**)&pGh,       g_gh);
    cudaGetSymbolAddress((void**)&pGx,       g_gx);
    cudaGetSymbolAddress((void**)&pProp,     g_prop);
    cudaGetSymbolAddress((void**)&pA3,       g_A3);
    cudaGetSymbolAddress((void**)&pMerged3,  g_merged3);
    cudaGetSymbolAddress((void**)&pProj,     g_proj);

    const int BIG = 1 << 30;

    zero_init_kernel<<<2 * EE * (KK + 1), 256>>>(src, dst, nbrs);
    last_occ_kernel<<<(EE + 255) / 256, 256>>>(src, dst);

    // merge(src) / merge(dst):  [E2 x 400] @ [400 x 200], tanh
    prep_A1_kernel<<<E2, 256>>>(mem_s, mem_g, src, dst);
    {
        dim3 grid((MM + 63) / 64, E2 / 128);
        gemm_tc<<<grid, 256>>>(pA1, 400, 0, 0, 400, W_merge, W_merge, b_merge, b_merge, BIG,
                               pMerged12, MM, MM, 1);
    }
    // messages: [E2 x 572] @ [572 x 100], relu
    prep_Amsg_kernel<<<E2, 256>>>(efeats, eidx);
    {
        dim3 grid((DM + 63) / 64, E2 / 128);
        gemm_tc<<<grid, 256>>>(pAmsg, 572, 0, 0, 572, W_msg, W_msg, b_msg, b_msg, BIG,
                               pMsgs, DM, DM, 2);
    }
    // GRU gates: gh = h @ Wh (h sliced out of g_A1 via aOff), gx = msg @ Wx + bg
    {
        dim3 grid((600 + 63) / 64, E2 / 128);
        gemm_tc<<<grid, 256>>>(pA1, 400, 0, 200, 200, Wh_s, Wh_g, nullptr, nullptr, EE,
                               pGh, 600, 600, 0);
        gemm_tc<<<grid, 256>>>(pMsgs, DM, 0, 0, DM, Wx_s, Wx_g, bg_s, bg_g, EE,
                               pGx, 600, 600, 0);
    }
    // prop = tanh(msg @ W_prop)
    {
        dim3 grid((MM + 63) / 64, E2 / 128);
        gemm_tc<<<grid, 256>>>(pMsgs, DM, 0, 0, DM, Wp_s, Wp_g, nullptr, nullptr, EE,
                               pProp, MM, MM, 1);
    }
    gru_scatter_kernel<<<E2, 256>>>(src, dst, nbrs, etimes, lu_s, lu_g);

    // score path
    prep_A3_kernel<<<E3, 256>>>(mem_s, mem_g, src, dst, neg);
    {
        dim3 grid((MM + 63) / 64, E3 / 128);
        gemm_tc<<<grid, 256>>>(pA3, 400, 0, 0, 400, W_merge, W_merge, b_merge, b_merge, BIG,
                               pMerged3, MM, MM, 1);
    }
    {
        dim3 grid((DM + 63) / 64, E3 / 128);
        gemm_tc<<<grid, 256>>>(pMerged3, MM, 0, 0, MM, W_s, W_g, nullptr, nullptr, EE,
                               pProj, DM, DM, 0);
    }
    score_kernel<<<(E2 * 32 + 255) / 256, 256>>>(out);
}

// round 4
// speedup vs baseline: 1.6743x; 1.0927x over previous
#include <cuda_runtime.h>
#include <cuda_bf16.h>
#include <cstdint>

// Problem constants
#define NN 200000
#define MM 200
#define DM 100
#define DE 172
#define EE 8192
#define KK 10
#define TAU 2.0f

#define E2 (2*EE)     // 16384
#define E3 (3*EE)     // 24576

// ----------------- persistent scratch (zero-initialized at load) -----------------
__device__ float g_merged12[E2 * MM];
__device__ float g_msgs[E2 * DM];
__device__ float g_gh[E2 * 600];
__device__ float g_gx[E2 * 600];
__device__ float g_prop[E2 * MM];
__device__ float g_delta_s[(long)NN * MM];
__device__ float g_delta_g[(long)NN * MM];
__device__ int   g_last_s[NN];
__device__ int   g_last_g[NN];
__device__ float g_merged3[E3 * MM];
__device__ float g_proj[E3 * DM];

// ----------------- zero / init touched rows (warp per task) -----------------
#define NTASKS (2*EE*(KK+1))   // 180224
__global__ void zero_init_kernel(const int* __restrict__ src, const int* __restrict__ dst,
                                 const int* __restrict__ neighbors)
{
    int t = blockIdx.x * 8 + (threadIdx.x >> 5);
    int lane = threadIdx.x & 31;
    if (t >= NTASKS) return;
    float* delta;
    int node;
    if (t < EE) {
        node = src[t]; delta = g_delta_s;
        if (lane == 0) g_last_s[node] = -1;
    } else if (t < E2) {
        node = dst[t - EE]; delta = g_delta_g;
        if (lane == 0) g_last_g[node] = -1;
    } else if (t < E2 + EE*KK) {
        int q = t - E2;
        node = neighbors[(long)src[q / KK] * KK + (q % KK)];
        delta = g_delta_s;
    } else {
        int q = t - E2 - EE*KK;
        node = neighbors[(long)dst[q / KK] * KK + (q % KK)];
        delta = g_delta_g;
    }
    #pragma unroll
    for (int m = lane; m < MM; m += 32) delta[(long)node * MM + m] = 0.0f;
}

__global__ void last_occ_kernel(const int* __restrict__ src, const int* __restrict__ dst)
{
    int e = blockIdx.x * blockDim.x + threadIdx.x;
    if (e >= EE) return;
    atomicMax(&g_last_s[src[e]], e);
    atomicMax(&g_last_g[dst[e]], e);
}

// ----------------- tf32 tensor-core GEMM, pipelined, gather-fused -----------------
// MODE 0: A[r][k] = A[r*lda + k]                         (plain)
// MODE 1: A[r][k] = k<200 ? ms[n][k] : mg[n][k-200],  n = r<E?src[r]:dst[r-E]
// MODE 2: same as 1 plus +delta,  n over {src,dst,neg} thirds
// MODE 3: A[r][k] = k<200 ? m12[r][k] : k<400 ? m12[(r+E)%2E][k-200] : ef[eidx[e]][k-400]
// MODE 4: A[r][k] = (r<E ? ms[src[r]] : mg[dst[r-E]])[k]
// C = act(A@B + bias); B/bias switch at blockRow >= rowSwitch (rowSwitch % 128 == 0).
__device__ __forceinline__ uint32_t f2tf32(float f) {
    uint32_t r;
    asm("cvt.rna.tf32.f32 %0, %1;" : "=r"(r) : "f"(f));
    return r;
}
__device__ __forceinline__ void mma_tf32(float* c, const uint32_t* a, const uint32_t* b) {
    asm volatile("mma.sync.aligned.m16n8k8.row.col.f32.tf32.tf32.f32 "
                 "{%0,%1,%2,%3}, {%4,%5,%6,%7}, {%8,%9}, {%0,%1,%2,%3};"
                 : "+f"(c[0]), "+f"(c[1]), "+f"(c[2]), "+f"(c[3])
                 : "r"(a[0]), "r"(a[1]), "r"(a[2]), "r"(a[3]),
                   "r"(b[0]), "r"(b[1]));
}

#define ASTRIDE 40
#define BSTRIDE 72
#define ABUF (128*ASTRIDE)     // 5120
#define BBUF (32*BSTRIDE)      // 2304
#define SMEM_BYTES ((2*ABUF + 2*BBUF) * 4)   // 59392

template<int MODE>
__global__ __launch_bounds__(256) void gemm_tc(
    const float* __restrict__ A, int lda, int Kdim,
    const float* __restrict__ P0, const float* __restrict__ P1,
    const float* __restrict__ D0, const float* __restrict__ D1,
    const int* __restrict__ i0, const int* __restrict__ i1, const int* __restrict__ i2,
    const float* __restrict__ EF, const int* __restrict__ EIDX,
    const float* __restrict__ B0, const float* __restrict__ B1,
    const float* __restrict__ bias0, const float* __restrict__ bias1, int rowSwitch,
    float* __restrict__ C, int Ndim, int act)
{
    extern __shared__ uint32_t sm[];
    uint32_t* AsBuf[2] = { sm, sm + ABUF };
    uint32_t* BsBuf[2] = { sm + 2*ABUF, sm + 2*ABUF + BBUF };

    int blockRow = blockIdx.y * 128;
    int blockCol = blockIdx.x * 64;
    bool firstSide = blockRow < rowSwitch;
    const float* B    = firstSide ? B0 : B1;
    const float* bias = firstSide ? bias0 : bias1;

    int tid = threadIdx.x, lane = tid & 31, warp = tid >> 5;
    int wm = (warp & 3) * 32, wn = (warp >> 2) * 32;
    int g = lane >> 2, tg = lane & 3;

    // Per-slice row base pointers (row fixed across K tiles -> hoisted)
    const float* rp0[4]; const float* rp1[4]; const float* rp2[4]; const float* rp3[4];
    #pragma unroll
    for (int i = 0; i < 4; i++) {
        int r = blockRow + ((tid + i*256) >> 3);
        if (MODE == 0) {
            rp0[i] = A + (long)r * lda;
        } else if (MODE == 1) {
            int node = (r < EE) ? i0[r] : i1[r - EE];
            rp0[i] = P0 + (long)node * MM;
            rp1[i] = P1 + (long)node * MM;
        } else if (MODE == 2) {
            int node = (r < EE) ? i0[r] : ((r < E2) ? i1[r - EE] : i2[r - E2]);
            rp0[i] = P0 + (long)node * MM;
            rp1[i] = P1 + (long)node * MM;
            rp2[i] = D0 + (long)node * MM;
            rp3[i] = D1 + (long)node * MM;
        } else if (MODE == 3) {
            int e  = (r < EE) ? r : r - EE;
            int r2 = (r < EE) ? (r + EE) : (r - EE);
            rp0[i] = A + (long)r * MM;
            rp1[i] = A + (long)r2 * MM;
            rp2[i] = EF + (long)EIDX[e] * DE;
        } else {
            int node = (r < EE) ? i0[r] : i1[r - EE];
            rp0[i] = ((r < EE) ? P0 : P1) + (long)node * MM;
        }
    }

    float4 ra[4]; float4 rb[2];
    auto loadA = [&](int k0) {
        #pragma unroll
        for (int i = 0; i < 4; i++) {
            int q = (tid + i*256) & 7;
            int k = k0 + q * 4;
            float4 v = make_float4(0.f, 0.f, 0.f, 0.f);
            if (MODE == 0) {
                if (k < Kdim) v = *(const float4*)(rp0[i] + k);
            } else if (MODE == 1) {
                if (k < MM)        v = *(const float4*)(rp0[i] + k);
                else if (k < 2*MM) v = *(const float4*)(rp1[i] + k - MM);
            } else if (MODE == 2) {
                if (k < MM) {
                    float4 a = *(const float4*)(rp0[i] + k);
                    float4 d = *(const float4*)(rp2[i] + k);
                    v = make_float4(a.x+d.x, a.y+d.y, a.z+d.z, a.w+d.w);
                } else if (k < 2*MM) {
                    float4 a = *(const float4*)(rp1[i] + k - MM);
                    float4 d = *(const float4*)(rp3[i] + k - MM);
                    v = make_float4(a.x+d.x, a.y+d.y, a.z+d.z, a.w+d.w);
                }
            } else if (MODE == 3) {
                if (k < MM)             v = *(const float4*)(rp0[i] + k);
                else if (k < 2*MM)      v = *(const float4*)(rp1[i] + k - MM);
                else if (k < 2*MM + DE) v = *(const float4*)(rp2[i] + k - 2*MM);
            } else {
                if (k < MM) v = *(const float4*)(rp0[i] + k);
            }
            ra[i] = v;
        }
    };
    auto loadB = [&](int k0) {
        #pragma unroll
        for (int i = 0; i < 2; i++) {
            int idx = tid + i*256;
            int kr = idx >> 4, n4 = (idx & 15) * 4;
            int k = k0 + kr, n = blockCol + n4;
            float4 v = make_float4(0.f, 0.f, 0.f, 0.f);
            if (k < Kdim && n < Ndim) v = *(const float4*)&B[(long)k * Ndim + n];
            rb[i] = v;
        }
    };
    // A staged with intra-slab interleave + row-xor swizzle:
    // element (r, k): pos = 8*(k/8) + 2*(k%4) + ((k%8)/4), stored at (pos ^ 2*(r&3)).
    auto stsA = [&](uint32_t* dst) {
        #pragma unroll
        for (int i = 0; i < 4; i++) {
            int idx = tid + i*256;
            int r = idx >> 3, q = idx & 7;
            int slab = q >> 1, half = q & 1;
            int base = r * ASTRIDE;
            int swz = (r & 3) * 2;
            const float* v = (const float*)&ra[i];
            #pragma unroll
            for (int j = 0; j < 4; j++) {
                int pos = (slab*8 + half + 2*j) ^ swz;
                dst[base + pos] = f2tf32(v[j]);
            }
        }
    };
    auto stsB = [&](uint32_t* dst) {
        #pragma unroll
        for (int i = 0; i < 2; i++) {
            int idx = tid + i*256;
            int kr = idx >> 4, n4 = (idx & 15) * 4;
            const float* v = (const float*)&rb[i];
            uint4 t;
            t.x = f2tf32(v[0]); t.y = f2tf32(v[1]);
            t.z = f2tf32(v[2]); t.w = f2tf32(v[3]);
            *(uint4*)&dst[kr * BSTRIDE + n4] = t;
        }
    };

    float acc[2][4][4];
    #pragma unroll
    for (int i = 0; i < 2; i++)
        #pragma unroll
        for (int j = 0; j < 4; j++)
            #pragma unroll
            for (int q = 0; q < 4; q++) acc[i][j][q] = 0.0f;

    int nTiles = (Kdim + 31) / 32;
    loadA(0); loadB(0);
    stsA(AsBuf[0]); stsB(BsBuf[0]);
    __syncthreads();

    for (int t = 0; t < nTiles; t++) {
        int cur = t & 1, nxt = cur ^ 1;
        bool more = (t + 1 < nTiles);
        if (more) { loadA((t+1)*32); loadB((t+1)*32); }

        const uint32_t* Asm = AsBuf[cur];
        const uint32_t* Bsm = BsBuf[cur];
        #pragma unroll
        for (int ks = 0; ks < 4; ks++) {
            uint32_t a[2][4], b[4][2];
            #pragma unroll
            for (int mt = 0; mt < 2; mt++) {
                int mr = wm + mt*16 + g;
                int swz = (mr & 3) * 2;
                int p = (ks*8 + 2*tg) ^ swz;
                uint2 v0 = *(const uint2*)&Asm[mr * ASTRIDE + p];
                uint2 v1 = *(const uint2*)&Asm[(mr + 8) * ASTRIDE + p];
                a[mt][0] = v0.x; a[mt][2] = v0.y;
                a[mt][1] = v1.x; a[mt][3] = v1.y;
            }
            #pragma unroll
            for (int nt = 0; nt < 4; nt++) {
                int nc = wn + nt*8 + g;
                b[nt][0] = Bsm[(ks*8 + tg) * BSTRIDE + nc];
                b[nt][1] = Bsm[(ks*8 + tg + 4) * BSTRIDE + nc];
            }
            #pragma unroll
            for (int mt = 0; mt < 2; mt++)
                #pragma unroll
                for (int nt = 0; nt < 4; nt++)
                    mma_tf32(acc[mt][nt], a[mt], b[nt]);
        }
        if (more) { stsA(AsBuf[nxt]); stsB(BsBuf[nxt]); }
        __syncthreads();
    }

    // Epilogue
    #pragma unroll
    for (int mt = 0; mt < 2; mt++) {
        #pragma unroll
        for (int nt = 0; nt < 4; nt++) {
            int r0 = blockRow + wm + mt*16 + g;
            int c0 = blockCol + wn + nt*8 + tg*2;
            float bv0 = 0.0f, bv1 = 0.0f;
            if (bias) {
                if (c0     < Ndim) bv0 = bias[c0];
                if (c0 + 1 < Ndim) bv1 = bias[c0 + 1];
            }
            #pragma unroll
            for (int q = 0; q < 4; q++) {
                int r = r0 + (q >> 1) * 8;
                int c = c0 + (q & 1);
                if (c >= Ndim) continue;
                float v = acc[mt][nt][q] + ((q & 1) ? bv1 : bv0);
                if (act == 1) v = tanhf(v);
                else if (act == 2) v = fmaxf(v, 0.0f);
                C[(long)r * Ndim + c] = v;
            }
        }
    }
}

// ----------------- GRU + neighbor-propagation scatter -----------------
__device__ __forceinline__ float sigmoidf_(float x) { return 1.0f / (1.0f + expf(-x)); }

__global__ void gru_scatter_kernel(const float* __restrict__ mem_s, const float* __restrict__ mem_g,
                                   const int* __restrict__ src, const int* __restrict__ dst,
                                   const int* __restrict__ neighbors,
                                   const float* __restrict__ times,
                                   const float* __restrict__ lu_s, const float* __restrict__ lu_g)
{
    int row = blockIdx.x;                 // 0..2E
    bool sideS = (row < EE);
    int e = sideS ? row : (row - EE);
    int node = sideS ? src[e] : dst[e];
    int last = sideS ? g_last_s[node] : g_last_g[node];
    if (last != e) return;
    int m = threadIdx.x;
    if (m >= MM) return;

    float* delta = sideS ? g_delta_s : g_delta_g;
    const float* lu = sideS ? lu_s : lu_g;

    float h = (sideS ? mem_s : mem_g)[(long)node * MM + m];
    long gb = (long)row * 600;
    float rx = g_gx[gb + m], zx = g_gx[gb + MM + m], nx = g_gx[gb + 2*MM + m];
    float rh = g_gh[gb + m], zh = g_gh[gb + MM + m], nh = g_gh[gb + 2*MM + m];
    float r = sigmoidf_(rx + rh);
    float z = sigmoidf_(zx + zh);
    float n = tanhf(nx + r * nh);
    float new_h = (1.0f - z) * n + z * h;
    atomicAdd(&delta[(long)node * MM + m], new_h - h);

    float p = g_prop[(long)row * MM + m];
    float t = times[e];
    #pragma unroll
    for (int k = 0; k < KK; k++) {
        int nb = neighbors[(long)node * KK + k];
        float dt = t - lu[nb];
        dt = fminf(fmaxf(dt, 0.0f), 50.0f);
        float decay = expf(-dt * (1.0f / TAU));
        atomicAdd(&delta[(long)nb * MM + m], decay * p);
    }
}

// ----------------- final dot + sigmoid -----------------
__global__ void score_kernel(float* __restrict__ out)
{
    int gw = (blockIdx.x * blockDim.x + threadIdx.x) >> 5;
    int lane = threadIdx.x & 31;
    if (gw >= E2) return;
    int e = (gw < EE) ? gw : (gw - EE);
    const float* u = g_proj + (long)e * DM;
    const float* v = g_proj + (long)((gw < EE) ? (EE + e) : (E2 + e)) * DM;
    float s = 0.0f;
    for (int c = lane; c < DM; c += 32) s += u[c] * v[c];
    #pragma unroll
    for (int off = 16; off > 0; off >>= 1) s += __shfl_down_sync(0xffffffffu, s, off);
    if (lane == 0) out[gw] = 1.0f / (1.0f + expf(-s));
}

// ----------------- launch -----------------
extern "C" void kernel_launch(void* const* d_in, const int* in_sizes, int n_in,
                              void* d_out, int out_size)
{
    const float* mem_s   = (const float*)d_in[0];
    const float* mem_g   = (const float*)d_in[1];
    const float* lu_s    = (const float*)d_in[2];
    const float* lu_g    = (const float*)d_in[3];
    const float* efeats  = (const float*)d_in[4];
    const float* etimes  = (const float*)d_in[5];
    const int*   src     = (const int*)d_in[6];
    const int*   dst     = (const int*)d_in[7];
    const int*   neg     = (const int*)d_in[8];
    const int*   eidx    = (const int*)d_in[9];
    const int*   nbrs    = (const int*)d_in[10];
    const float* W_merge = (const float*)d_in[11];
    const float* b_merge = (const float*)d_in[12];
    const float* W_msg   = (const float*)d_in[13];
    const float* b_msg   = (const float*)d_in[14];
    const float* Wx_s    = (const float*)d_in[15];
    const float* Wh_s    = (const float*)d_in[16];
    const float* bg_s    = (const float*)d_in[17];
    const float* Wx_g    = (const float*)d_in[18];
    const float* Wh_g    = (const float*)d_in[19];
    const float* bg_g    = (const float*)d_in[20];
    const float* Wp_s    = (const float*)d_in[21];
    const float* Wp_g    = (const float*)d_in[22];
    const float* W_s     = (const float*)d_in[23];
    const float* W_g     = (const float*)d_in[24];
    float* out = (float*)d_out;

    float *pMerged12, *pMsgs, *pGh, *pGx, *pProp, *pDs, *pDg, *pMerged3, *pProj;
    cudaGetSymbolAddress((void**)&pMerged12, g_merged12);
    cudaGetSymbolAddress((void**)&pMsgs,     g_msgs);
    cudaGetSymbolAddress((void**)&pGh,       g_gh);
    cudaGetSymbolAddress((void**)&pGx,       g_gx);
    cudaGetSymbolAddress((void**)&pProp,     g_prop);
    cudaGetSymbolAddress((void**)&pDs,       g_delta_s);
    cudaGetSymbolAddress((void**)&pDg,       g_delta_g);
    cudaGetSymbolAddress((void**)&pMerged3,  g_merged3);
    cudaGetSymbolAddress((void**)&pProj,     g_proj);

    cudaFuncSetAttribute(gemm_tc<0>, cudaFuncAttributeMaxDynamicSharedMemorySize, SMEM_BYTES);
    cudaFuncSetAttribute(gemm_tc<1>, cudaFuncAttributeMaxDynamicSharedMemorySize, SMEM_BYTES);
    cudaFuncSetAttribute(gemm_tc<2>, cudaFuncAttributeMaxDynamicSharedMemorySize, SMEM_BYTES);
    cudaFuncSetAttribute(gemm_tc<3>, cudaFuncAttributeMaxDynamicSharedMemorySize, SMEM_BYTES);
    cudaFuncSetAttribute(gemm_tc<4>, cudaFuncAttributeMaxDynamicSharedMemorySize, SMEM_BYTES);

    const int BIG = 1 << 30;

    zero_init_kernel<<<NTASKS / 8, 256>>>(src, dst, nbrs);
    last_occ_kernel<<<(EE + 255) / 256, 256>>>(src, dst);

    // merge12 = tanh([ms|mg][src/dst] @ W_merge + b)   [E2 x 400] @ [400 x 200]
    gemm_tc<1><<<dim3(4, E2/128), 256, SMEM_BYTES>>>(
        nullptr, 0, 400, mem_s, mem_g, nullptr, nullptr, src, dst, nullptr,
        nullptr, nullptr, W_merge, W_merge, b_merge, b_merge, BIG,
        pMerged12, MM, 1);

    // msgs = relu(concat(m12_first, m12_second, ef) @ W_msg + b)  [E2 x 572] @ [572 x 100]
    gemm_tc<3><<<dim3(2, E2/128), 256, SMEM_BYTES>>>(
        pMerged12, 0, 572, nullptr, nullptr, nullptr, nullptr, nullptr, nullptr, nullptr,
        efeats, eidx, W_msg, W_msg, b_msg, b_msg, BIG,
        pMsgs, DM, 2);

    // gh = h @ Wh  (h gathered from mem_s[src] / mem_g[dst])  [E2 x 200] @ [200 x 600]
    gemm_tc<4><<<dim3(10, E2/128), 256, SMEM_BYTES>>>(
        nullptr, 0, 200, mem_s, mem_g, nullptr, nullptr, src, dst, nullptr,
        nullptr, nullptr, Wh_s, Wh_g, nullptr, nullptr, EE,
        pGh, 600, 0);

    // gx = msgs @ Wx + bg   [E2 x 100] @ [100 x 600]
    gemm_tc<0><<<dim3(10, E2/128), 256, SMEM_BYTES>>>(
        pMsgs, DM, DM, nullptr, nullptr, nullptr, nullptr, nullptr, nullptr, nullptr,
        nullptr, nullptr, Wx_s, Wx_g, bg_s, bg_g, EE,
        pGx, 600, 0);

    // prop = tanh(msgs @ W_prop)   [E2 x 100] @ [100 x 200]
    gemm_tc<0><<<dim3(4, E2/128), 256, SMEM_BYTES>>>(
        pMsgs, DM, DM, nullptr, nullptr, nullptr, nullptr, nullptr, nullptr, nullptr,
        nullptr, nullptr, Wp_s, Wp_g, nullptr, nullptr, EE,
        pProp, MM, 1);

    gru_scatter_kernel<<<E2, 256>>>(mem_s, mem_g, src, dst, nbrs, etimes, lu_s, lu_g);

    // merged3 = tanh([ms+ds | mg+dg][src/dst/neg] @ W_merge + b)  [E3 x 400] @ [400 x 200]
    gemm_tc<2><<<dim3(4, E3/128), 256, SMEM_BYTES>>>(
        nullptr, 0, 400, mem_s, mem_g, pDs, pDg, src, dst, neg,
        nullptr, nullptr, W_merge, W_merge, b_merge, b_merge, BIG,
        pMerged3, MM, 1);

    // proj = merged3 @ (W_s | W_g)   [E3 x 200] @ [200 x 100]
    gemm_tc<0><<<dim3(2, E3/128), 256, SMEM_BYTES>>>(
        pMerged3, MM, MM, nullptr, nullptr, nullptr, nullptr, nullptr, nullptr, nullptr,
        nullptr, nullptr, W_s, W_g, nullptr, nullptr, EE,
        pProj, DM, 0);

    score_kernel<<<(E2 * 32 + 255) / 256, 256>>>(out);
}

// round 7
// speedup vs baseline: 2.4022x; 1.4347x over previous
#include <cuda_runtime.h>
#include <cuda_bf16.h>
#include <cstdint>

// Problem constants
#define NN 200000
#define MM 200
#define DM 100
#define DE 172
#define EE 8192
#define KK 10
#define TAU 2.0f

#define E2 (2*EE)     // 16384
#define E3 (3*EE)     // 24576

// ----------------- persistent scratch (zero-initialized at load) -----------------
__device__ float g_merged12[E2 * MM];
__device__ float g_msgs[E2 * DM];
__device__ float g_gh[E2 * 600];
__device__ float g_gx[E2 * 600];
__device__ float g_prop[E2 * MM];
__device__ float g_delta_s[(long)NN * MM];
__device__ float g_delta_g[(long)NN * MM];
__device__ int   g_last_s[NN];
__device__ int   g_last_g[NN];
__device__ float g_A3[E3 * 400];
__device__ float g_merged3[E3 * MM];
__device__ float g_proj[E3 * DM];

// ----------------- zero / init touched rows (warp per task, float4) -----------------
#define NTASKS (2*EE*(KK+1))   // 180224
__global__ void zero_init_kernel(const int* __restrict__ src, const int* __restrict__ dst,
                                 const int* __restrict__ neighbors)
{
    int t = blockIdx.x * 8 + (threadIdx.x >> 5);
    int lane = threadIdx.x & 31;
    if (t >= NTASKS) return;
    float* delta;
    int node;
    if (t < EE) {
        node = src[t]; delta = g_delta_s;
        if (lane == 0) g_last_s[node] = -1;
    } else if (t < E2) {
        node = dst[t - EE]; delta = g_delta_g;
        if (lane == 0) g_last_g[node] = -1;
    } else if (t < E2 + EE*KK) {
        int q = t - E2;
        node = neighbors[(long)src[q / KK] * KK + (q % KK)];
        delta = g_delta_s;
    } else {
        int q = t - E2 - EE*KK;
        node = neighbors[(long)dst[q / KK] * KK + (q % KK)];
        delta = g_delta_g;
    }
    float4* p = (float4*)(delta + (long)node * MM);
    float4 z = make_float4(0.f, 0.f, 0.f, 0.f);
    #pragma unroll
    for (int c = lane; c < MM/4; c += 32) p[c] = z;
}

__global__ void last_occ_kernel(const int* __restrict__ src, const int* __restrict__ dst)
{
    int e = blockIdx.x * blockDim.x + threadIdx.x;
    if (e >= EE) return;
    atomicMax(&g_last_s[src[e]], e);
    atomicMax(&g_last_g[dst[e]], e);
}

// A3 = [mem+delta] gathered for {src,dst,neg}  (float4, warp per row)
__global__ void prep_A3_kernel(const float* __restrict__ mem_s, const float* __restrict__ mem_g,
                               const int* __restrict__ src, const int* __restrict__ dst,
                               const int* __restrict__ neg)
{
    int r = blockIdx.x * 8 + (threadIdx.x >> 5);
    int lane = threadIdx.x & 31;
    if (r >= E3) return;
    int idx = (r < EE) ? src[r] : ((r < E2) ? dst[r - EE] : neg[r - E2]);
    const float4* ps = (const float4*)(mem_s + (long)idx * MM);
    const float4* pg = (const float4*)(mem_g + (long)idx * MM);
    const float4* ds = (const float4*)(g_delta_s + (long)idx * MM);
    const float4* dg = (const float4*)(g_delta_g + (long)idx * MM);
    float4* o = (float4*)(g_A3 + (long)r * 400);
    #pragma unroll
    for (int c = lane; c < 100; c += 32) {
        float4 a = (c < 50) ? ps[c] : pg[c - 50];
        float4 d = (c < 50) ? ds[c] : dg[c - 50];
        o[c] = make_float4(a.x + d.x, a.y + d.y, a.z + d.z, a.w + d.w);
    }
}

// ----------------- tf32 tensor-core GEMM, cp.async 3-stage pipeline -----------------
// MODE 0: A[r][k] = A[r*lda + k]
// MODE 1: A[r][k] = k<200 ? P0[n][k] : P1[n][k-200],  n = r<E?i0[r]:i1[r-E]
// MODE 3: A[r][k] = k<200 ? A[r][k] : k<400 ? A[r_other][k-200] : EF[EIDX[e]][k-400]
// MODE 4: A[r][k] = (r<E ? P0[i0[r]] : P1[i1[r-E]])[k]
__device__ __forceinline__ uint32_t f2tf32(float f) {
    uint32_t r;
    asm("cvt.rna.tf32.f32 %0, %1;" : "=r"(r) : "f"(f));
    return r;
}
__device__ __forceinline__ void mma_tf32(float* c, const uint32_t* a, const uint32_t* b) {
    asm volatile("mma.sync.aligned.m16n8k8.row.col.f32.tf32.tf32.f32 "
                 "{%0,%1,%2,%3}, {%4,%5,%6,%7}, {%8,%9}, {%0,%1,%2,%3};"
                 : "+f"(c[0]), "+f"(c[1]), "+f"(c[2]), "+f"(c[3])
                 : "r"(a[0]), "r"(a[1]), "r"(a[2]), "r"(a[3]),
                   "r"(b[0]), "r"(b[1]));
}
__device__ __forceinline__ void cp_async16(uint32_t dst, const void* src, int sz) {
    asm volatile("cp.async.cg.shared.global [%0], [%1], 16, %2;"
                 :: "r"(dst), "l"(src), "r"(sz) : "memory");
}
__device__ __forceinline__ void cp_commit() { asm volatile("cp.async.commit_group;" ::: "memory"); }
template<int N> __device__ __forceinline__ void cp_wait() {
    asm volatile("cp.async.wait_group %0;" :: "n"(N) : "memory");
}
__device__ __forceinline__ uint32_t smem_u32(const void* p) {
    uint32_t a;
    asm("{ .reg .u64 t; cvta.to.shared.u64 t, %1; cvt.u32.u64 %0, t; }" : "=r"(a) : "l"(p));
    return a;
}

#define ASTRIDE 36
#define AWORDS (128*ASTRIDE)               // 4608
#define BSTRIDE 72
#define BWORDS (32*BSTRIDE)                // 2304
#define STAGE_WORDS (AWORDS + BWORDS)      // 6912
#define NSTAGE 3
#define SMEM_BYTES (NSTAGE*STAGE_WORDS*4)  // 82944

template<int MODE>
__global__ __launch_bounds__(256) void gemm_tc(
    const float* __restrict__ A, int lda, int Kdim,
    const float* __restrict__ P0, const float* __restrict__ P1,
    const int* __restrict__ i0, const int* __restrict__ i1,
    const float* __restrict__ EF, const int* __restrict__ EIDX,
    const float* __restrict__ B0, const float* __restrict__ B1,
    const float* __restrict__ bias0, const float* __restrict__ bias1, int rowSwitch,
    float* __restrict__ C, int Ndim, int act)
{
    extern __shared__ float smf[];
    uint32_t smemBase = smem_u32(smf);

    int blockRow = blockIdx.y * 128;
    int blockCol = blockIdx.x * 64;
    bool firstSide = blockRow < rowSwitch;
    const float* B    = firstSide ? B0 : B1;
    const float* bias = firstSide ? bias0 : bias1;

    int tid = threadIdx.x, lane = tid & 31, warp = tid >> 5;
    int wm = (warp & 3) * 32, wn = (warp >> 2) * 32;
    int g = lane >> 2, tg = lane & 3;

    // Per-chunk row base pointers (fixed across K tiles)
    const float* rp0[4]; const float* rp1[4]; const float* rp2[4];
    #pragma unroll
    for (int i = 0; i < 4; i++) {
        int r = blockRow + ((tid + i*256) >> 3);
        if (MODE == 0) {
            rp0[i] = A + (long)r * lda;
        } else if (MODE == 1) {
            int node = (r < EE) ? i0[r] : i1[r - EE];
            rp0[i] = P0 + (long)node * MM;
            rp1[i] = P1 + (long)node * MM;
        } else if (MODE == 3) {
            int e  = (r < EE) ? r : r - EE;
            int r2 = (r < EE) ? (r + EE) : (r - EE);
            rp0[i] = A + (long)r * MM;
            rp1[i] = A + (long)r2 * MM;
            rp2[i] = EF + (long)EIDX[e] * DE;
        } else {
            int node = (r < EE) ? i0[r] : i1[r - EE];
            rp0[i] = ((r < EE) ? P0 : P1) + (long)node * MM;
        }
    }

    auto issue = [&](int t) {
        int s = t % NSTAGE;
        uint32_t aB = smemBase + (uint32_t)(s * STAGE_WORDS) * 4u;
        uint32_t bB = aB + AWORDS * 4u;
        int k0 = t * 32;
        #pragma unroll
        for (int i = 0; i < 4; i++) {
            int idx = tid + i*256;
            int rl = idx >> 3, q = idx & 7;
            int k = k0 + q * 4;
            uint32_t dst = aB + (uint32_t)(rl * ASTRIDE + q * 4) * 4u;
            const float* src; int sz = 16;
            if (MODE == 0) {
                src = rp0[i] + k; if (k >= Kdim) sz = 0;
            } else if (MODE == 1) {
                src = (k < MM) ? rp0[i] + k : rp1[i] + k - MM;   // Kdim=400, all valid
            } else if (MODE == 3) {
                if (k < MM)        src = rp0[i] + k;
                else if (k < 2*MM) src = rp1[i] + k - MM;
                else { src = rp2[i] + k - 2*MM; if (k >= 2*MM + DE) sz = 0; }
            } else {
                src = rp0[i] + k; if (k >= MM) sz = 0;           // Kdim=200
            }
            cp_async16(dst, src, sz);
        }
        #pragma unroll
        for (int i = 0; i < 2; i++) {
            int idx = tid + i*256;
            int kr = idx >> 4, n4 = (idx & 15) * 4;
            int k = k0 + kr, n = blockCol + n4;
            uint32_t dst = bB + (uint32_t)(kr * BSTRIDE + n4) * 4u;
            const float* src = B + (long)k * Ndim + n;
            int sz = (k < Kdim && n < Ndim) ? 16 : 0;
            cp_async16(dst, src, sz);
        }
    };

    float acc[2][4][4];
    #pragma unroll
    for (int i = 0; i < 2; i++)
        #pragma unroll
        for (int j = 0; j < 4; j++)
            #pragma unroll
            for (int q = 0; q < 4; q++) acc[i][j][q] = 0.0f;

    int nT = (Kdim + 31) / 32;
    issue(0); cp_commit();
    if (nT > 1) issue(1);
    cp_commit();

    for (int t = 0; t < nT; t++) {
        cp_wait<1>();
        __syncthreads();
        const uint32_t* Asm = (const uint32_t*)smf + (t % NSTAGE) * STAGE_WORDS;
        const uint32_t* Bsm = Asm + AWORDS;
        #pragma unroll
        for (int ks = 0; ks < 4; ks++) {
            uint32_t a[2][4], b[4][2];
            #pragma unroll
            for (int mt = 0; mt < 2; mt++) {
                int mr = wm + mt*16 + g;
                const uint32_t* ar0 = &Asm[(mr    ) * ASTRIDE + ks*8];
                const uint32_t* ar1 = &Asm[(mr + 8) * ASTRIDE + ks*8];
                // fragment k-pairing (tg, tg+4) — MUST match B below
                a[mt][0] = f2tf32(__uint_as_float(ar0[tg]));
                a[mt][1] = f2tf32(__uint_as_float(ar1[tg]));
                a[mt][2] = f2tf32(__uint_as_float(ar0[tg + 4]));
                a[mt][3] = f2tf32(__uint_as_float(ar1[tg + 4]));
            }
            #pragma unroll
            for (int nt = 0; nt < 4; nt++) {
                int nc = wn + nt*8 + g;
                b[nt][0] = f2tf32(__uint_as_float(Bsm[(ks*8 + tg) * BSTRIDE + nc]));
                b[nt][1] = f2tf32(__uint_as_float(Bsm[(ks*8 + tg + 4) * BSTRIDE + nc]));
            }
            #pragma unroll
            for (int mt = 0; mt < 2; mt++)
                #pragma unroll
                for (int nt = 0; nt < 4; nt++)
                    mma_tf32(acc[mt][nt], a[mt], b[nt]);
        }
        if (t + 2 < nT) issue(t + 2);
        cp_commit();
    }

    // Epilogue
    #pragma unroll
    for (int mt = 0; mt < 2; mt++) {
        #pragma unroll
        for (int nt = 0; nt < 4; nt++) {
            int r0 = blockRow + wm + mt*16 + g;
            int c0 = blockCol + wn + nt*8 + tg*2;
            float bv0 = 0.0f, bv1 = 0.0f;
            if (bias) {
                if (c0     < Ndim) bv0 = bias[c0];
                if (c0 + 1 < Ndim) bv1 = bias[c0 + 1];
            }
            #pragma unroll
            for (int q = 0; q < 4; q++) {
                int r = r0 + (q >> 1) * 8;
                int c = c0 + (q & 1);
                if (c >= Ndim) continue;
                float v = acc[mt][nt][q] + ((q & 1) ? bv1 : bv0);
                if (act == 1) v = tanhf(v);
                else if (act == 2) v = fmaxf(v, 0.0f);
                C[(long)r * Ndim + c] = v;
            }
        }
    }
}

// ----------------- GRU + neighbor-propagation scatter -----------------
__device__ __forceinline__ float sigmoidf_(float x) { return 1.0f / (1.0f + expf(-x)); }

__global__ void gru_scatter_kernel(const float* __restrict__ mem_s, const float* __restrict__ mem_g,
                                   const int* __restrict__ src, const int* __restrict__ dst,
                                   const int* __restrict__ neighbors,
                                   const float* __restrict__ times,
                                   const float* __restrict__ lu_s, const float* __restrict__ lu_g)
{
    int row = blockIdx.x;                 // 0..2E
    bool sideS = (row < EE);
    int e = sideS ? row : (row - EE);
    int node = sideS ? src[e] : dst[e];
    int last = sideS ? g_last_s[node] : g_last_g[node];
    if (last != e) return;
    int m = threadIdx.x;
    if (m >= MM) return;

    float* delta = sideS ? g_delta_s : g_delta_g;
    const float* lu = sideS ? lu_s : lu_g;

    float h = (sideS ? mem_s : mem_g)[(long)node * MM + m];
    long gb = (long)row * 600;
    float rx = g_gx[gb + m], zx = g_gx[gb + MM + m], nx = g_gx[gb + 2*MM + m];
    float rh = g_gh[gb + m], zh = g_gh[gb + MM + m], nh = g_gh[gb + 2*MM + m];
    float r = sigmoidf_(rx + rh);
    float z = sigmoidf_(zx + zh);
    float n = tanhf(nx + r * nh);
    float new_h = (1.0f - z) * n + z * h;
    atomicAdd(&delta[(long)node * MM + m], new_h - h);

    float p = g_prop[(long)row * MM + m];
    float t = times[e];
    #pragma unroll
    for (int k = 0; k < KK; k++) {
        int nb = neighbors[(long)node * KK + k];
        float dt = t - lu[nb];
        dt = fminf(fmaxf(dt, 0.0f), 50.0f);
        float decay = expf(-dt * (1.0f / TAU));
        atomicAdd(&delta[(long)nb * MM + m], decay * p);
    }
}

// ----------------- final dot + sigmoid -----------------
__global__ void score_kernel(float* __restrict__ out)
{
    int gw = (blockIdx.x * blockDim.x + threadIdx.x) >> 5;
    int lane = threadIdx.x & 31;
    if (gw >= E2) return;
    int e = (gw < EE) ? gw : (gw - EE);
    const float* u = g_proj + (long)e * DM;
    const float* v = g_proj + (long)((gw < EE) ? (EE + e) : (E2 + e)) * DM;
    float s = 0.0f;
    for (int c = lane; c < DM; c += 32) s += u[c] * v[c];
    #pragma unroll
    for (int off = 16; off > 0; off >>= 1) s += __shfl_down_sync(0xffffffffu, s, off);
    if (lane == 0) out[gw] = 1.0f / (1.0f + expf(-s));
}

// ----------------- launch -----------------
extern "C" void kernel_launch(void* const* d_in, const int* in_sizes, int n_in,
                              void* d_out, int out_size)
{
    const float* mem_s   = (const float*)d_in[0];
    const float* mem_g   = (const float*)d_in[1];
    const float* lu_s    = (const float*)d_in[2];
    const float* lu_g    = (const float*)d_in[3];
    const float* efeats  = (const float*)d_in[4];
    const float* etimes  = (const float*)d_in[5];
    const int*   src     = (const int*)d_in[6];
    const int*   dst     = (const int*)d_in[7];
    const int*   neg     = (const int*)d_in[8];
    const int*   eidx    = (const int*)d_in[9];
    const int*   nbrs    = (const int*)d_in[10];
    const float* W_merge = (const float*)d_in[11];
    const float* b_merge = (const float*)d_in[12];
    const float* W_msg   = (const float*)d_in[13];
    const float* b_msg   = (const float*)d_in[14];
    const float* Wx_s    = (const float*)d_in[15];
    const float* Wh_s    = (const float*)d_in[16];
    const float* bg_s    = (const float*)d_in[17];
    const float* Wx_g    = (const float*)d_in[18];
    const float* Wh_g    = (const float*)d_in[19];
    const float* bg_g    = (const float*)d_in[20];
    const float* Wp_s    = (const float*)d_in[21];
    const float* Wp_g    = (const float*)d_in[22];
    const float* W_s     = (const float*)d_in[23];
    const float* W_g     = (const float*)d_in[24];
    float* out = (float*)d_out;

    float *pMerged12, *pMsgs, *pGh, *pGx, *pProp, *pA3, *pMerged3, *pProj;
    cudaGetSymbolAddress((void**)&pMerged12, g_merged12);
    cudaGetSymbolAddress((void**)&pMsgs,     g_msgs);
    cudaGetSymbolAddress((void**)&pGh,       g_gh);
    cudaGetSymbolAddress((void**)&pGx,       g_gx);
    cudaGetSymbolAddress((void**)&pProp,     g_prop);
    cudaGetSymbolAddress((void**)&pA3,       g_A3);
    cudaGetSymbolAddress((void**)&pMerged3,  g_merged3);
    cudaGetSymbolAddress((void**)&pProj,     g_proj);

    cudaFuncSetAttribute(gemm_tc<0>, cudaFuncAttributeMaxDynamicSharedMemorySize, SMEM_BYTES);
    cudaFuncSetAttribute(gemm_tc<1>, cudaFuncAttributeMaxDynamicSharedMemorySize, SMEM_BYTES);
    cudaFuncSetAttribute(gemm_tc<3>, cudaFuncAttributeMaxDynamicSharedMemorySize, SMEM_BYTES);
    cudaFuncSetAttribute(gemm_tc<4>, cudaFuncAttributeMaxDynamicSharedMemorySize, SMEM_BYTES);

    const int BIG = 1 << 30;

    zero_init_kernel<<<NTASKS / 8, 256>>>(src, dst, nbrs);
    last_occ_kernel<<<(EE + 255) / 256, 256>>>(src, dst);

    // merge12 = tanh([ms|mg][src/dst] @ W_merge + b)   [E2 x 400] @ [400 x 200]
    gemm_tc<1><<<dim3(4, E2/128), 256, SMEM_BYTES>>>(
        nullptr, 0, 400, mem_s, mem_g, src, dst, nullptr, nullptr,
        W_merge, W_merge, b_merge, b_merge, BIG, pMerged12, MM, 1);

    // msgs = relu(concat(m12_a, m12_b, ef) @ W_msg + b)  [E2 x 572] @ [572 x 100]
    gemm_tc<3><<<dim3(2, E2/128), 256, SMEM_BYTES>>>(
        pMerged12, 0, 572, nullptr, nullptr, nullptr, nullptr, efeats, eidx,
        W_msg, W_msg, b_msg, b_msg, BIG, pMsgs, DM, 2);

    // gh = h @ Wh   [E2 x 200] @ [200 x 600]
    gemm_tc<4><<<dim3(10, E2/128), 256, SMEM_BYTES>>>(
        nullptr, 0, 200, mem_s, mem_g, src, dst, nullptr, nullptr,
        Wh_s, Wh_g, nullptr, nullptr, EE, pGh, 600, 0);

    // gx = msgs @ Wx + bg   [E2 x 100] @ [100 x 600]
    gemm_tc<0><<<dim3(10, E2/128), 256, SMEM_BYTES>>>(
        pMsgs, DM, DM, nullptr, nullptr, nullptr, nullptr, nullptr, nullptr,
        Wx_s, Wx_g, bg_s, bg_g, EE, pGx, 600, 0);

    // prop = tanh(msgs @ W_prop)   [E2 x 100] @ [100 x 200]
    gemm_tc<0><<<dim3(4, E2/128), 256, SMEM_BYTES>>>(
        pMsgs, DM, DM, nullptr, nullptr, nullptr, nullptr, nullptr, nullptr,
        Wp_s, Wp_g, nullptr, nullptr, EE, pProp, MM, 1);

    gru_scatter_kernel<<<E2, 256>>>(mem_s, mem_g, src, dst, nbrs, etimes, lu_s, lu_g);

    // merged3 path: materialize A3 = [mem+delta] gathered, then plain GEMM
    prep_A3_kernel<<<E3/8, 256>>>(mem_s, mem_g, src, dst, neg);
    gemm_tc<0><<<dim3(4, E3/128), 256, SMEM_BYTES>>>(
        pA3, 400, 400, nullptr, nullptr, nullptr, nullptr, nullptr, nullptr,
        W_merge, W_merge, b_merge, b_merge, BIG, pMerged3, MM, 1);

    // proj = merged3 @ (W_s | W_g)   [E3 x 200] @ [200 x 100]
    gemm_tc<0><<<dim3(2, E3/128), 256, SMEM_BYTES>>>(
        pMerged3, MM, MM, nullptr, nullptr, nullptr, nullptr, nullptr, nullptr,
        W_s, W_g, nullptr, nullptr, EE, pProj, DM, 0);

    score_kernel<<<(E2 * 32 + 255) / 256, 256>>>(out);
}

// round 8
// speedup vs baseline: 2.4185x; 1.0068x over previous
#include <cuda_runtime.h>
#include <cuda_bf16.h>
#include <cstdint>

// Problem constants
#define NN 200000
#define MM 200
#define DM 100
#define DE 172
#define EE 8192
#define KK 10
#define TAU 2.0f

#define E2 (2*EE)     // 16384
#define E3 (3*EE)     // 24576

// ----------------- persistent scratch (zero-initialized at load) -----------------
__device__ float g_merged12[E2 * MM];
__device__ float g_msgs[E2 * DM];
__device__ float g_gh[E2 * 600];
__device__ float g_gx[E2 * 600];
__device__ float g_prop[E2 * MM];
__device__ float g_delta_s[(long)NN * MM];
__device__ float g_delta_g[(long)NN * MM];
__device__ int   g_last_s[NN];
__device__ int   g_last_g[NN];
__device__ float g_A3[E3 * 400];
__device__ float g_merged3[E3 * MM];
__device__ float g_proj[E3 * DM];
__device__ float g_ef[EE * DE];        // per-edge gathered + tf32-rounded edge feats

// tf32-rounded weight copies (concatenated)
#define OFF_WMERGE 0
#define OFF_WMSG   80000
#define OFF_WXS    137200
#define OFF_WXG    197200
#define OFF_WHS    257200
#define OFF_WHG    377200
#define OFF_WPS    497200
#define OFF_WPG    517200
#define OFF_WS     537200
#define OFF_WG     557200
#define WCVT_TOTAL 577200
__device__ float g_wcvt[WCVT_TOTAL];

__device__ __forceinline__ uint32_t f2tf32(float f) {
    uint32_t r;
    asm("cvt.rna.tf32.f32 %0, %1;" : "=r"(r) : "f"(f));
    return r;
}
__device__ __forceinline__ float roundtf(float f) { return __uint_as_float(f2tf32(f)); }

// ----------------- weight conversion (once per launch) -----------------
__global__ void cvt_weights_kernel(const float* __restrict__ wm, const float* __restrict__ wmsg,
                                   const float* __restrict__ wxs, const float* __restrict__ wxg,
                                   const float* __restrict__ whs, const float* __restrict__ whg,
                                   const float* __restrict__ wps, const float* __restrict__ wpg,
                                   const float* __restrict__ ws,  const float* __restrict__ wg)
{
    int i = blockIdx.x * blockDim.x + threadIdx.x;
    if (i >= WCVT_TOTAL) return;
    const float* s; int o;
    if      (i < OFF_WMSG) { s = wm;   o = i - OFF_WMERGE; }
    else if (i < OFF_WXS)  { s = wmsg; o = i - OFF_WMSG; }
    else if (i < OFF_WXG)  { s = wxs;  o = i - OFF_WXS; }
    else if (i < OFF_WHS)  { s = wxg;  o = i - OFF_WXG; }
    else if (i < OFF_WHG)  { s = whs;  o = i - OFF_WHS; }
    else if (i < OFF_WPS)  { s = whg;  o = i - OFF_WHG; }
    else if (i < OFF_WPG)  { s = wps;  o = i - OFF_WPS; }
    else if (i < OFF_WS)   { s = wpg;  o = i - OFF_WPG; }
    else if (i < OFF_WG)   { s = ws;   o = i - OFF_WS; }
    else                   { s = wg;   o = i - OFF_WG; }
    g_wcvt[i] = roundtf(s[o]);
}

// gather + round edge feats per edge
__global__ void prep_ef_kernel(const float* __restrict__ edge_feats, const int* __restrict__ eidx)
{
    int e = blockIdx.x * 8 + (threadIdx.x >> 5);
    int lane = threadIdx.x & 31;
    if (e >= EE) return;
    const float4* s = (const float4*)(edge_feats + (long)eidx[e] * DE);
    float4* o = (float4*)(g_ef + (long)e * DE);
    #pragma unroll
    for (int c = lane; c < DE/4; c += 32) {
        float4 v = s[c];
        o[c] = make_float4(roundtf(v.x), roundtf(v.y), roundtf(v.z), roundtf(v.w));
    }
}

// ----------------- zero / init touched rows -----------------
#define NTASKS (2*EE*(KK+1))   // 180224
__global__ void zero_init_kernel(const int* __restrict__ src, const int* __restrict__ dst,
                                 const int* __restrict__ neighbors)
{
    int t = blockIdx.x * 8 + (threadIdx.x >> 5);
    int lane = threadIdx.x & 31;
    if (t >= NTASKS) return;
    float* delta;
    int node;
    if (t < EE) {
        node = src[t]; delta = g_delta_s;
        if (lane == 0) g_last_s[node] = -1;
    } else if (t < E2) {
        node = dst[t - EE]; delta = g_delta_g;
        if (lane == 0) g_last_g[node] = -1;
    } else if (t < E2 + EE*KK) {
        int q = t - E2;
        node = neighbors[(long)src[q / KK] * KK + (q % KK)];
        delta = g_delta_s;
    } else {
        int q = t - E2 - EE*KK;
        node = neighbors[(long)dst[q / KK] * KK + (q % KK)];
        delta = g_delta_g;
    }
    float4* p = (float4*)(delta + (long)node * MM);
    float4 z = make_float4(0.f, 0.f, 0.f, 0.f);
    #pragma unroll
    for (int c = lane; c < MM/4; c += 32) p[c] = z;
}

__global__ void last_occ_kernel(const int* __restrict__ src, const int* __restrict__ dst)
{
    int e = blockIdx.x * blockDim.x + threadIdx.x;
    if (e >= EE) return;
    atomicMax(&g_last_s[src[e]], e);
    atomicMax(&g_last_g[dst[e]], e);
}

// A3 = round(mem+delta) gathered for {src,dst,neg}
__global__ void prep_A3_kernel(const float* __restrict__ mem_s, const float* __restrict__ mem_g,
                               const int* __restrict__ src, const int* __restrict__ dst,
                               const int* __restrict__ neg)
{
    int r = blockIdx.x * 8 + (threadIdx.x >> 5);
    int lane = threadIdx.x & 31;
    if (r >= E3) return;
    int idx = (r < EE) ? src[r] : ((r < E2) ? dst[r - EE] : neg[r - E2]);
    const float4* ps = (const float4*)(mem_s + (long)idx * MM);
    const float4* pg = (const float4*)(mem_g + (long)idx * MM);
    const float4* ds = (const float4*)(g_delta_s + (long)idx * MM);
    const float4* dg = (const float4*)(g_delta_g + (long)idx * MM);
    float4* o = (float4*)(g_A3 + (long)r * 400);
    #pragma unroll
    for (int c = lane; c < 100; c += 32) {
        float4 a = (c < 50) ? ps[c] : pg[c - 50];
        float4 d = (c < 50) ? ds[c] : dg[c - 50];
        o[c] = make_float4(roundtf(a.x + d.x), roundtf(a.y + d.y),
                           roundtf(a.z + d.z), roundtf(a.w + d.w));
    }
}

// ----------------- tf32 tensor-core GEMM, cp.async 3-stage pipeline -----------------
// MODE 0: A[r][k] = A[r*lda + k]
// MODE 1: A[r][k] = k<200 ? P0[n][k] : P1[n][k-200],  n = r<E?i0[r]:i1[r-E]
// MODE 3: A[r][k] = k<200 ? A[r][k] : k<400 ? A[r_other][k-200] : g_ef[e][k-400]
// MODE 4: A[r][k] = (r<E ? P0[i0[r]] : P1[i1[r-E]])[k]
// B rows are stored K-permuted (per 8-slab: logical k -> phys (k&1 ? k/2+4 : k/2))
// so that A fragments load logical k=(2tg, 2tg+1) as one LDS.64.
__device__ __forceinline__ void mma_tf32(float* c, const uint32_t* a, const uint32_t* b) {
    asm volatile("mma.sync.aligned.m16n8k8.row.col.f32.tf32.tf32.f32 "
                 "{%0,%1,%2,%3}, {%4,%5,%6,%7}, {%8,%9}, {%0,%1,%2,%3};"
                 : "+f"(c[0]), "+f"(c[1]), "+f"(c[2]), "+f"(c[3])
                 : "r"(a[0]), "r"(a[1]), "r"(a[2]), "r"(a[3]),
                   "r"(b[0]), "r"(b[1]));
}
__device__ __forceinline__ void cp_async16(uint32_t dst, const void* src, int sz) {
    asm volatile("cp.async.cg.shared.global [%0], [%1], 16, %2;"
                 :: "r"(dst), "l"(src), "r"(sz) : "memory");
}
__device__ __forceinline__ void cp_commit() { asm volatile("cp.async.commit_group;" ::: "memory"); }
template<int N> __device__ __forceinline__ void cp_wait() {
    asm volatile("cp.async.wait_group %0;" :: "n"(N) : "memory");
}
__device__ __forceinline__ uint32_t smem_u32(const void* p) {
    uint32_t a;
    asm("{ .reg .u64 t; cvta.to.shared.u64 t, %1; cvt.u32.u64 %0, t; }" : "=r"(a) : "l"(p));
    return a;
}

#define ASTRIDE 40
#define AWORDS (128*ASTRIDE)               // 5120
#define BSTRIDE 72
#define BWORDS (32*BSTRIDE)                // 2304
#define STAGE_WORDS (AWORDS + BWORDS)      // 7424
#define NSTAGE 3
#define SMEM_BYTES (NSTAGE*STAGE_WORDS*4)  // 89088

template<int MODE, bool CVTA>
__global__ __launch_bounds__(256) void gemm_tc(
    const float* __restrict__ A, int lda, int Kdim,
    const float* __restrict__ P0, const float* __restrict__ P1,
    const int* __restrict__ i0, const int* __restrict__ i1,
    const float* __restrict__ B0, const float* __restrict__ B1,
    const float* __restrict__ bias0, const float* __restrict__ bias1, int rowSwitch,
    float* __restrict__ C, int Ndim, int act, int roundOut)
{
    extern __shared__ float smf[];
    uint32_t smemBase = smem_u32(smf);

    int blockRow = blockIdx.y * 128;
    int blockCol = blockIdx.x * 64;
    bool firstSide = blockRow < rowSwitch;
    const float* B    = firstSide ? B0 : B1;
    const float* bias = firstSide ? bias0 : bias1;

    int tid = threadIdx.x, lane = tid & 31, warp = tid >> 5;
    int wm = (warp & 3) * 32, wn = (warp >> 2) * 32;
    int g = lane >> 2, tg = lane & 3;

    // Per-chunk row base pointers (fixed across K tiles)
    const float* rp0[4]; const float* rp1[4]; const float* rp2[4];
    #pragma unroll
    for (int i = 0; i < 4; i++) {
        int r = blockRow + ((tid + i*256) >> 3);
        if (MODE == 0) {
            rp0[i] = A + (long)r * lda;
        } else if (MODE == 1) {
            int node = (r < EE) ? i0[r] : i1[r - EE];
            rp0[i] = P0 + (long)node * MM;
            rp1[i] = P1 + (long)node * MM;
        } else if (MODE == 3) {
            int e  = (r < EE) ? r : r - EE;
            int r2 = (r < EE) ? (r + EE) : (r - EE);
            rp0[i] = A + (long)r * MM;
            rp1[i] = A + (long)r2 * MM;
            rp2[i] = g_ef + (long)e * DE;
        } else {
            int node = (r < EE) ? i0[r] : i1[r - EE];
            rp0[i] = ((r < EE) ? P0 : P1) + (long)node * MM;
        }
    }

    auto issue = [&](int t) {
        int s = t % NSTAGE;
        uint32_t aB = smemBase + (uint32_t)(s * STAGE_WORDS) * 4u;
        uint32_t bB = aB + AWORDS * 4u;
        int k0 = t * 32;
        #pragma unroll
        for (int i = 0; i < 4; i++) {
            int idx = tid + i*256;
            int rl = idx >> 3, q = idx & 7;
            int k = k0 + q * 4;
            uint32_t dst = aB + (uint32_t)(rl * ASTRIDE + q * 4) * 4u;
            const float* src; int sz = 16;
            if (MODE == 0) {
                src = rp0[i] + k; if (k >= Kdim) sz = 0;
            } else if (MODE == 1) {
                src = (k < MM) ? rp0[i] + k : rp1[i] + k - MM;   // Kdim=400
            } else if (MODE == 3) {
                if (k < MM)        src = rp0[i] + k;
                else if (k < 2*MM) src = rp1[i] + k - MM;
                else { src = rp2[i] + k - 2*MM; if (k >= 2*MM + DE) sz = 0; }
            } else {
                src = rp0[i] + k; if (k >= MM) sz = 0;           // Kdim=200
            }
            cp_async16(dst, src, sz);
        }
        #pragma unroll
        for (int i = 0; i < 2; i++) {
            int idx = tid + i*256;
            int kr = idx >> 4, n4 = (idx & 15) * 4;
            int k = k0 + kr, n = blockCol + n4;
            // K-permuted destination row (per 8-slab interleave)
            int l = kr & 7;
            int phys = (kr & ~7) + ((l & 1) ? (l >> 1) + 4 : (l >> 1));
            uint32_t dst = bB + (uint32_t)(phys * BSTRIDE + n4) * 4u;
            const float* src = B + (long)k * Ndim + n;
            int sz = (k < Kdim && n < Ndim) ? 16 : 0;
            cp_async16(dst, src, sz);
        }
    };

    float acc[2][4][4];
    #pragma unroll
    for (int i = 0; i < 2; i++)
        #pragma unroll
        for (int j = 0; j < 4; j++)
            #pragma unroll
            for (int q = 0; q < 4; q++) acc[i][j][q] = 0.0f;

    int nT = (Kdim + 31) / 32;
    issue(0); cp_commit();
    if (nT > 1) issue(1);
    cp_commit();

    for (int t = 0; t < nT; t++) {
        cp_wait<1>();
        __syncthreads();
        const uint32_t* Asm = (const uint32_t*)smf + (t % NSTAGE) * STAGE_WORDS;
        const uint32_t* Bsm = Asm + AWORDS;
        #pragma unroll
        for (int ks = 0; ks < 4; ks++) {
            uint32_t a[2][4], b[4][2];
            #pragma unroll
            for (int mt = 0; mt < 2; mt++) {
                int mr = wm + mt*16 + g;
                // logical k = (2tg, 2tg+1): one conflict-free LDS.64 per row
                uint2 v0 = *(const uint2*)&Asm[(mr    ) * ASTRIDE + ks*8 + 2*tg];
                uint2 v1 = *(const uint2*)&Asm[(mr + 8) * ASTRIDE + ks*8 + 2*tg];
                if (CVTA) {
                    a[mt][0] = f2tf32(__uint_as_float(v0.x));
                    a[mt][2] = f2tf32(__uint_as_float(v0.y));
                    a[mt][1] = f2tf32(__uint_as_float(v1.x));
                    a[mt][3] = f2tf32(__uint_as_float(v1.y));
                } else {
                    a[mt][0] = v0.x; a[mt][2] = v0.y;
                    a[mt][1] = v1.x; a[mt][3] = v1.y;
                }
            }
            #pragma unroll
            for (int nt = 0; nt < 4; nt++) {
                int nc = wn + nt*8 + g;
                b[nt][0] = Bsm[(ks*8 + tg) * BSTRIDE + nc];       // logical k=2tg (permuted)
                b[nt][1] = Bsm[(ks*8 + tg + 4) * BSTRIDE + nc];   // logical k=2tg+1
            }
            #pragma unroll
            for (int mt = 0; mt < 2; mt++)
                #pragma unroll
                for (int nt = 0; nt < 4; nt++)
                    mma_tf32(acc[mt][nt], a[mt], b[nt]);
        }
        if (t + 2 < nT) issue(t + 2);
        cp_commit();
    }

    // Epilogue
    #pragma unroll
    for (int mt = 0; mt < 2; mt++) {
        #pragma unroll
        for (int nt = 0; nt < 4; nt++) {
            int r0 = blockRow + wm + mt*16 + g;
            int c0 = blockCol + wn + nt*8 + tg*2;
            float bv0 = 0.0f, bv1 = 0.0f;
            if (bias) {
                if (c0     < Ndim) bv0 = bias[c0];
                if (c0 + 1 < Ndim) bv1 = bias[c0 + 1];
            }
            #pragma unroll
            for (int q = 0; q < 4; q++) {
                int r = r0 + (q >> 1) * 8;
                int c = c0 + (q & 1);
                if (c >= Ndim) continue;
                float v = acc[mt][nt][q] + ((q & 1) ? bv1 : bv0);
                if (act == 1) v = tanhf(v);
                else if (act == 2) v = fmaxf(v, 0.0f);
                if (roundOut) v = roundtf(v);
                C[(long)r * Ndim + c] = v;
            }
        }
    }
}

// ----------------- GRU + neighbor-propagation scatter -----------------
__device__ __forceinline__ float sigmoidf_(float x) { return 1.0f / (1.0f + expf(-x)); }

__global__ void gru_scatter_kernel(const float* __restrict__ mem_s, const float* __restrict__ mem_g,
                                   const int* __restrict__ src, const int* __restrict__ dst,
                                   const int* __restrict__ neighbors,
                                   const float* __restrict__ times,
                                   const float* __restrict__ lu_s, const float* __restrict__ lu_g)
{
    int row = blockIdx.x;                 // 0..2E
    bool sideS = (row < EE);
    int e = sideS ? row : (row - EE);
    int node = sideS ? src[e] : dst[e];
    int last = sideS ? g_last_s[node] : g_last_g[node];
    if (last != e) return;
    int m = threadIdx.x;
    if (m >= MM) return;

    float* delta = sideS ? g_delta_s : g_delta_g;
    const float* lu = sideS ? lu_s : lu_g;

    float h = (sideS ? mem_s : mem_g)[(long)node * MM + m];
    long gb = (long)row * 600;
    float rx = g_gx[gb + m], zx = g_gx[gb + MM + m], nx = g_gx[gb + 2*MM + m];
    float rh = g_gh[gb + m], zh = g_gh[gb + MM + m], nh = g_gh[gb + 2*MM + m];
    float r = sigmoidf_(rx + rh);
    float z = sigmoidf_(zx + zh);
    float n = tanhf(nx + r * nh);
    float new_h = (1.0f - z) * n + z * h;
    atomicAdd(&delta[(long)node * MM + m], new_h - h);

    float p = g_prop[(long)row * MM + m];
    float t = times[e];
    #pragma unroll
    for (int k = 0; k < KK; k++) {
        int nb = neighbors[(long)node * KK + k];
        float dt = t - lu[nb];
        dt = fminf(fmaxf(dt, 0.0f), 50.0f);
        float decay = expf(-dt * (1.0f / TAU));
        atomicAdd(&delta[(long)nb * MM + m], decay * p);
    }
}

// ----------------- final dot + sigmoid -----------------
__global__ void score_kernel(float* __restrict__ out)
{
    int gw = (blockIdx.x * blockDim.x + threadIdx.x) >> 5;
    int lane = threadIdx.x & 31;
    if (gw >= E2) return;
    int e = (gw < EE) ? gw : (gw - EE);
    const float* u = g_proj + (long)e * DM;
    const float* v = g_proj + (long)((gw < EE) ? (EE + e) : (E2 + e)) * DM;
    float s = 0.0f;
    for (int c = lane; c < DM; c += 32) s += u[c] * v[c];
    #pragma unroll
    for (int off = 16; off > 0; off >>= 1) s += __shfl_down_sync(0xffffffffu, s, off);
    if (lane == 0) out[gw] = 1.0f / (1.0f + expf(-s));
}

// ----------------- launch -----------------
extern "C" void kernel_launch(void* const* d_in, const int* in_sizes, int n_in,
                              void* d_out, int out_size)
{
    const float* mem_s   = (const float*)d_in[0];
    const float* mem_g   = (const float*)d_in[1];
    const float* lu_s    = (const float*)d_in[2];
    const float* lu_g    = (const float*)d_in[3];
    const float* efeats  = (const float*)d_in[4];
    const float* etimes  = (const float*)d_in[5];
    const int*   src     = (const int*)d_in[6];
    const int*   dst     = (const int*)d_in[7];
    const int*   neg     = (const int*)d_in[8];
    const int*   eidx    = (const int*)d_in[9];
    const int*   nbrs    = (const int*)d_in[10];
    const float* W_merge = (const float*)d_in[11];
    const float* b_merge = (const float*)d_in[12];
    const float* W_msg   = (const float*)d_in[13];
    const float* b_msg   = (const float*)d_in[14];
    const float* Wx_s    = (const float*)d_in[15];
    const float* Wh_s    = (const float*)d_in[16];
    const float* bg_s    = (const float*)d_in[17];
    const float* Wx_g    = (const float*)d_in[18];
    const float* Wh_g    = (const float*)d_in[19];
    const float* bg_g    = (const float*)d_in[20];
    const float* Wp_s    = (const float*)d_in[21];
    const float* Wp_g    = (const float*)d_in[22];
    const float* W_s     = (const float*)d_in[23];
    const float* W_g     = (const float*)d_in[24];
    float* out = (float*)d_out;

    float *pMerged12, *pMsgs, *pGh, *pGx, *pProp, *pA3, *pMerged3, *pProj, *pW;
    cudaGetSymbolAddress((void**)&pMerged12, g_merged12);
    cudaGetSymbolAddress((void**)&pMsgs,     g_msgs);
    cudaGetSymbolAddress((void**)&pGh,       g_gh);
    cudaGetSymbolAddress((void**)&pGx,       g_gx);
    cudaGetSymbolAddress((void**)&pProp,     g_prop);
    cudaGetSymbolAddress((void**)&pA3,       g_A3);
    cudaGetSymbolAddress((void**)&pMerged3,  g_merged3);
    cudaGetSymbolAddress((void**)&pProj,     g_proj);
    cudaGetSymbolAddress((void**)&pW,        g_wcvt);

    cudaFuncSetAttribute(gemm_tc<0,false>, cudaFuncAttributeMaxDynamicSharedMemorySize, SMEM_BYTES);
    cudaFuncSetAttribute(gemm_tc<1,true>,  cudaFuncAttributeMaxDynamicSharedMemorySize, SMEM_BYTES);
    cudaFuncSetAttribute(gemm_tc<3,false>, cudaFuncAttributeMaxDynamicSharedMemorySize, SMEM_BYTES);
    cudaFuncSetAttribute(gemm_tc<4,true>,  cudaFuncAttributeMaxDynamicSharedMemorySize, SMEM_BYTES);

    const int BIG = 1 << 30;

    cvt_weights_kernel<<<(WCVT_TOTAL + 255) / 256, 256>>>(
        W_merge, W_msg, Wx_s, Wx_g, Wh_s, Wh_g, Wp_s, Wp_g, W_s, W_g);
    prep_ef_kernel<<<EE/8, 256>>>(efeats, eidx);
    zero_init_kernel<<<NTASKS / 8, 256>>>(src, dst, nbrs);
    last_occ_kernel<<<(EE + 255) / 256, 256>>>(src, dst);

    const float* cWm   = pW + OFF_WMERGE;
    const float* cWmsg = pW + OFF_WMSG;
    const float* cWxs  = pW + OFF_WXS;
    const float* cWxg  = pW + OFF_WXG;
    const float* cWhs  = pW + OFF_WHS;
    const float* cWhg  = pW + OFF_WHG;
    const float* cWps  = pW + OFF_WPS;
    const float* cWpg  = pW + OFF_WPG;
    const float* cWs   = pW + OFF_WS;
    const float* cWg   = pW + OFF_WG;

    // merge12 = round(tanh([ms|mg][src/dst] @ Wm + b))   [E2 x 400]x[400 x 200]
    gemm_tc<1,true><<<dim3(4, E2/128), 256, SMEM_BYTES>>>(
        nullptr, 0, 400, mem_s, mem_g, src, dst,
        cWm, cWm, b_merge, b_merge, BIG, pMerged12, MM, 1, 1);

    // msgs = round(relu(concat(m12_a, m12_b, ef) @ Wmsg + b))  [E2 x 572]x[572 x 100]
    gemm_tc<3,false><<<dim3(2, E2/128), 256, SMEM_BYTES>>>(
        pMerged12, 0, 572, nullptr, nullptr, nullptr, nullptr,
        cWmsg, cWmsg, b_msg, b_msg, BIG, pMsgs, DM, 2, 1);

    // gh = h @ Wh   [E2 x 200]x[200 x 600]
    gemm_tc<4,true><<<dim3(10, E2/128), 256, SMEM_BYTES>>>(
        nullptr, 0, 200, mem_s, mem_g, src, dst,
        cWhs, cWhg, nullptr, nullptr, EE, pGh, 600, 0, 0);

    // gx = msgs @ Wx + bg   [E2 x 100]x[100 x 600]
    gemm_tc<0,false><<<dim3(10, E2/128), 256, SMEM_BYTES>>>(
        pMsgs, DM, DM, nullptr, nullptr, nullptr, nullptr,
        cWxs, cWxg, bg_s, bg_g, EE, pGx, 600, 0, 0);

    // prop = tanh(msgs @ Wp)   [E2 x 100]x[100 x 200]
    gemm_tc<0,false><<<dim3(4, E2/128), 256, SMEM_BYTES>>>(
        pMsgs, DM, DM, nullptr, nullptr, nullptr, nullptr,
        cWps, cWpg, nullptr, nullptr, EE, pProp, MM, 1, 0);

    gru_scatter_kernel<<<E2, 256>>>(mem_s, mem_g, src, dst, nbrs, etimes, lu_s, lu_g);

    // merged3 path: A3 = round(mem+delta), then plain GEMM
    prep_A3_kernel<<<E3/8, 256>>>(mem_s, mem_g, src, dst, neg);
    gemm_tc<0,false><<<dim3(4, E3/128), 256, SMEM_BYTES>>>(
        pA3, 400, 400, nullptr, nullptr, nullptr, nullptr,
        cWm, cWm, b_merge, b_merge, BIG, pMerged3, MM, 1, 1);

    // proj = merged3 @ (W_s | W_g)   [E3 x 200]x[200 x 100]
    gemm_tc<0,false><<<dim3(2, E3/128), 256, SMEM_BYTES>>>(
        pMerged3, MM, MM, nullptr, nullptr, nullptr, nullptr,
        cWs, cWg, nullptr, nullptr, EE, pProj, DM, 0, 0);

    score_kernel<<<(E2 * 32 + 255) / 256, 256>>>(out);
}